// round 15
// baseline (speedup 1.0000x reference)
#include <cuda_runtime.h>
#include <cuda_fp16.h>
#include <cstdint>

// ---------------- problem constants ----------------
#define BB    32
#define NN    512
#define CC    512
#define HH    8
#define DHD   64
#define ADIM  8
#define MLPD  4096
#define MROWS (BB*NN)          // 16384

// ---------------- static device scratch ----------------
__device__ __align__(16) float  g_x  [(size_t)MROWS*CC];
__device__ __align__(16) __half g_h  [(size_t)MROWS*CC];
__device__ __align__(16) __half g_hb [(size_t)MROWS*CC];
__device__ __align__(16) __half g_qkv[(size_t)MROWS*3*CC];
__device__ __align__(16) __half g_ao [(size_t)MROWS*CC];
__device__ __align__(16) __half g_mlp[(size_t)MROWS*MLPD];
__device__ __align__(16) float  g_d  [(size_t)MROWS*ADIM];
__device__ __align__(16) float  g_c  [(size_t)MROWS*ADIM];
__device__ __align__(16) __half g_wqkvT[(size_t)3*CC*CC];
__device__ __align__(16) __half g_wprojT[(size_t)CC*CC];
__device__ __align__(16) __half g_wff1T[(size_t)MLPD*CC];
__device__ __align__(16) __half g_wff2T[(size_t)CC*MLPD];

// ---------------- helpers ----------------
__device__ __forceinline__ float qgelu(float v) { return v / (1.0f + __expf(-1.702f * v)); }
__device__ __forceinline__ float gelu_exact(float v) { return 0.5f * v * (1.0f + erff(v * 0.70710678118654752f)); }
__device__ __forceinline__ float ex2(float x) {
    float r; asm("ex2.approx.f32 %0, %1;" : "=f"(r) : "f"(x)); return r;
}
__device__ __forceinline__ uint32_t smem_u32(const void* p) {
    uint32_t a;
    asm("{ .reg .u64 t; cvta.to.shared.u64 t, %1; cvt.u32.u64 %0, t; }" : "=r"(a) : "l"(p));
    return a;
}
__device__ __forceinline__ void cp16(uint32_t saddr, const void* g) {
    asm volatile("cp.async.cg.shared.global [%0], [%1], 16;" :: "r"(saddr), "l"(g));
}
__device__ __forceinline__ void mma_fp16(float d[4], const uint32_t a[4], const uint32_t b[2]) {
    asm volatile("mma.sync.aligned.m16n8k16.row.col.f32.f16.f16.f32 "
        "{%0,%1,%2,%3}, {%4,%5,%6,%7}, {%8,%9}, {%0,%1,%2,%3};"
        : "+f"(d[0]), "+f"(d[1]), "+f"(d[2]), "+f"(d[3])
        : "r"(a[0]), "r"(a[1]), "r"(a[2]), "r"(a[3]), "r"(b[0]), "r"(b[1]));
}
#define LDSM_X4(r0, r1, r2, r3, addr) \
    asm volatile("ldmatrix.sync.aligned.m8n8.x4.shared.b16 {%0,%1,%2,%3}, [%4];" \
        : "=r"(r0), "=r"(r1), "=r"(r2), "=r"(r3) : "r"(addr))
#define LDSM_X4_T(r0, r1, r2, r3, addr) \
    asm volatile("ldmatrix.sync.aligned.m8n8.x4.trans.shared.b16 {%0,%1,%2,%3}, [%4];" \
        : "=r"(r0), "=r"(r1), "=r"(r2), "=r"(r3) : "r"(addr))
__device__ __forceinline__ uint32_t pack_half(float a, float b) {
    __half2 v = __floats2half2_rn(a, b);
    return *reinterpret_cast<uint32_t*>(&v);
}

__device__ __forceinline__ float blockReduceSum256(float v) {
    __shared__ float sh[8];
    int lane = threadIdx.x & 31, w = threadIdx.x >> 5;
    #pragma unroll
    for (int o = 16; o > 0; o >>= 1) v += __shfl_down_sync(0xffffffffu, v, o);
    if (lane == 0) sh[w] = v;
    __syncthreads();
    if (threadIdx.x < 8) {
        float t = sh[threadIdx.x];
        t += __shfl_down_sync(0xffu, t, 4);
        t += __shfl_down_sync(0xffu, t, 2);
        t += __shfl_down_sync(0xffu, t, 1);
        if (threadIdx.x == 0) sh[0] = t;
    }
    __syncthreads();
    float r = sh[0];
    __syncthreads();
    return r;
}

__device__ __forceinline__ void downReduceStore(float p[8], const float* __restrict__ db,
                                                float* __restrict__ dout, size_t row) {
    __shared__ float sh8[8][8];
    int lane = threadIdx.x & 31, w = threadIdx.x >> 5;
    #pragma unroll
    for (int a = 0; a < 8; ++a) {
        #pragma unroll
        for (int o = 16; o > 0; o >>= 1)
            p[a] += __shfl_down_sync(0xffffffffu, p[a], o);
    }
    if (lane == 0) {
        #pragma unroll
        for (int a = 0; a < 8; ++a) sh8[w][a] = p[a];
    }
    __syncthreads();
    if (threadIdx.x < 8) {
        float s = 0.f;
        #pragma unroll
        for (int ww = 0; ww < 8; ++ww) s += sh8[ww][threadIdx.x];
        dout[row * 8 + threadIdx.x] = qgelu(s + db[threadIdx.x]);
    }
}

// ---------------- fused (x+pos) + LN1 -> fp16 + adapter-down ----------------
__global__ __launch_bounds__(256) void add_ln_down(const float* __restrict__ xin,
                                                   const float* __restrict__ pos,
                                                   const float* __restrict__ g,
                                                   const float* __restrict__ b,
                                                   const float* __restrict__ dw,
                                                   const float* __restrict__ db,
                                                   float* __restrict__ xout,
                                                   __half* __restrict__ hout,
                                                   float* __restrict__ dout) {
    size_t row = blockIdx.x;
    int tid = threadIdx.x;
    float v0 = xin[row * CC + tid]       + pos[row * CC + tid];
    float v1 = xin[row * CC + tid + 256] + pos[row * CC + tid + 256];
    xout[row * CC + tid]       = v0;
    xout[row * CC + tid + 256] = v1;
    float mean = blockReduceSum256(v0 + v1) * (1.0f / 512.0f);
    float d0 = v0 - mean, d1 = v1 - mean;
    float var = blockReduceSum256(d0 * d0 + d1 * d1) * (1.0f / 512.0f);
    float inv = rsqrtf(var + 1e-5f);
    float h0 = d0 * inv * g[tid]       + b[tid];
    float h1 = d1 * inv * g[tid + 256] + b[tid + 256];
    hout[row * CC + tid]       = __float2half_rn(h0);
    hout[row * CC + tid + 256] = __float2half_rn(h1);
    float4 wA0 = *reinterpret_cast<const float4*>(dw + tid * 8);
    float4 wA1 = *reinterpret_cast<const float4*>(dw + tid * 8 + 4);
    float4 wB0 = *reinterpret_cast<const float4*>(dw + (tid + 256) * 8);
    float4 wB1 = *reinterpret_cast<const float4*>(dw + (tid + 256) * 8 + 4);
    float p[8];
    p[0] = h0 * wA0.x + h1 * wB0.x; p[1] = h0 * wA0.y + h1 * wB0.y;
    p[2] = h0 * wA0.z + h1 * wB0.z; p[3] = h0 * wA0.w + h1 * wB0.w;
    p[4] = h0 * wA1.x + h1 * wB1.x; p[5] = h0 * wA1.y + h1 * wB1.y;
    p[6] = h0 * wA1.z + h1 * wB1.z; p[7] = h0 * wA1.w + h1 * wB1.w;
    downReduceStore(p, db, dout, row);
}

// ---------------- LN2 + adapter-down ----------------
__global__ __launch_bounds__(256) void ln_h_down(const float* __restrict__ in,
                                                 const float* __restrict__ g,
                                                 const float* __restrict__ b,
                                                 const float* __restrict__ dw,
                                                 const float* __restrict__ db,
                                                 __half* __restrict__ out,
                                                 float* __restrict__ dout) {
    size_t row = blockIdx.x;
    int tid = threadIdx.x;
    float v0 = in[row * CC + tid], v1 = in[row * CC + tid + 256];
    float mean = blockReduceSum256(v0 + v1) * (1.0f / 512.0f);
    float d0 = v0 - mean, d1 = v1 - mean;
    float var = blockReduceSum256(d0 * d0 + d1 * d1) * (1.0f / 512.0f);
    float inv = rsqrtf(var + 1e-5f);
    float h0 = d0 * inv * g[tid]       + b[tid];
    float h1 = d1 * inv * g[tid + 256] + b[tid + 256];
    out[row * CC + tid]       = __float2half_rn(h0);
    out[row * CC + tid + 256] = __float2half_rn(h1);
    float4 wA0 = *reinterpret_cast<const float4*>(dw + tid * 8);
    float4 wA1 = *reinterpret_cast<const float4*>(dw + tid * 8 + 4);
    float4 wB0 = *reinterpret_cast<const float4*>(dw + (tid + 256) * 8);
    float4 wB1 = *reinterpret_cast<const float4*>(dw + (tid + 256) * 8 + 4);
    float p[8];
    p[0] = h0 * wA0.x + h1 * wB0.x; p[1] = h0 * wA0.y + h1 * wB0.y;
    p[2] = h0 * wA0.z + h1 * wB0.z; p[3] = h0 * wA0.w + h1 * wB0.w;
    p[4] = h0 * wA1.x + h1 * wB1.x; p[5] = h0 * wA1.y + h1 * wB1.y;
    p[6] = h0 * wA1.z + h1 * wB1.z; p[7] = h0 * wA1.w + h1 * wB1.w;
    downReduceStore(p, db, dout, row);
}

// ---------------- merged weight transpose ----------------
__global__ void transpose_all(const float* __restrict__ w0, __half* __restrict__ o0,
                              const float* __restrict__ w1, __half* __restrict__ o1,
                              const float* __restrict__ w2, __half* __restrict__ o2,
                              const float* __restrict__ w3, __half* __restrict__ o3) {
    __shared__ float t[32][33];
    int bid = blockIdx.x;
    const float* in; __half* out; int R, Cc, tx, ty;
    if (bid < 768)        { in = w0; out = o0; R = 512;  Cc = 1536; int l = bid;        tx = l % 48;  ty = l / 48; }
    else if (bid < 1024)  { in = w1; out = o1; R = 512;  Cc = 512;  int l = bid - 768;  tx = l % 16;  ty = l / 16; }
    else if (bid < 3072)  { in = w2; out = o2; R = 512;  Cc = 4096; int l = bid - 1024; tx = l % 128; ty = l / 128; }
    else                  { in = w3; out = o3; R = 4096; Cc = 512;  int l = bid - 3072; tx = l % 16;  ty = l / 16; }
    int bx = tx * 32, by = ty * 32;
    #pragma unroll
    for (int i = 0; i < 32; i += 8)
        t[threadIdx.y + i][threadIdx.x] = in[(size_t)(by + threadIdx.y + i) * Cc + bx + threadIdx.x];
    __syncthreads();
    #pragma unroll
    for (int i = 0; i < 32; i += 8)
        out[(size_t)(bx + threadIdx.y + i) * R + by + threadIdx.x] =
            __float2half_rn(t[threadIdx.x][threadIdx.y + i]);
}

// ---------------- fp16 mma GEMM, 256 thr, warp tile 64x32, templated NC -----------
// NC<=12: full unroll. NC>12: partial unroll 6 (period matches 3-buffer rotation,
// keeps code size inside L1.5 I$).
#define STG 32768
#define GEMM_SMEM (3*STG)      // 98304
template<int EPI, int NC>
__global__ __launch_bounds__(256, 2) void tc_gemm16(const __half* __restrict__ A,
                                                    const __half* __restrict__ BT,
                                                    const float* __restrict__ bias,
                                                    void* __restrict__ Cv,
                                                    int M, int N, int K,
                                                    const float* __restrict__ res,
                                                    const float* __restrict__ cpre,
                                                    const float* __restrict__ uw,
                                                    const float* __restrict__ ub) {
    extern __shared__ char smem[];
    const uint32_t sb = smem_u32(smem);
    const int tid = threadIdx.x;
    const int lane = tid & 31;
    const int w = tid >> 5;
    const int wm = w & 1, wn = w >> 1;
    const int g = lane >> 2, t = lane & 3;
    const int cRow = blockIdx.y * 128;
    const int cCol = blockIdx.x * 128;

    const int r_st = tid >> 3;
    const int j_st = tid & 7;

    const int rb = lane & 7;
    const int a_row = wm * 64 + (lane & 15);
    const int a_j0  = lane >> 4;
    const int b_row = wn * 32 + (lane & 7) + ((lane & 16) ? 8 : 0);
    const int b_j0  = (lane >> 3) & 1;

    float acc[4][4][4] = {};

    auto stage = [&](int kt, uint32_t abase) {
        const int k0 = kt << 6;
        const uint32_t bbase = abase + 16384;
        #pragma unroll
        for (int i = 0; i < 4; ++i) {
            int r = r_st + i * 32;
            uint32_t phys = (uint32_t)r * 128 + ((uint32_t)(j_st ^ (r & 7)) << 4);
            cp16(abase + phys, A + (size_t)(cRow + r) * K + k0 + j_st * 8);
            cp16(bbase + phys, BT + (size_t)(cCol + r) * K + k0 + j_st * 8);
        }
        asm volatile("cp.async.commit_group;" ::: "memory");
    };

    auto chunk = [&](int c, uint32_t As_u) {
        const uint32_t Bs_u = As_u + 16384;
        #pragma unroll
        for (int ks = 0; ks < 4; ++ks) {
            uint32_t af[4][4], bf[4][2];
            #pragma unroll
            for (int mf = 0; mf < 4; ++mf) {
                int row = a_row + mf * 16;
                uint32_t addr = As_u + (uint32_t)row * 128 +
                                ((uint32_t)((a_j0 + 2 * ks) ^ rb) << 4);
                LDSM_X4(af[mf][0], af[mf][1], af[mf][2], af[mf][3], addr);
            }
            #pragma unroll
            for (int p = 0; p < 2; ++p) {
                int row = b_row + p * 16;
                uint32_t addr = Bs_u + (uint32_t)row * 128 +
                                ((uint32_t)((b_j0 + 2 * ks) ^ rb) << 4);
                uint32_t r0, r1, r2, r3;
                LDSM_X4(r0, r1, r2, r3, addr);
                bf[2 * p][0] = r0; bf[2 * p][1] = r1;
                bf[2 * p + 1][0] = r2; bf[2 * p + 1][1] = r3;
            }
            #pragma unroll
            for (int mf = 0; mf < 4; ++mf)
                #pragma unroll
                for (int nf = 0; nf < 4; ++nf)
                    mma_fp16(acc[mf][nf], af[mf], bf[nf]);
        }
        if (c + 2 < NC)      { asm volatile("cp.async.wait_group 1;" ::: "memory"); }
        else if (c + 1 < NC) { asm volatile("cp.async.wait_group 0;" ::: "memory"); }
        __syncthreads();
        if (c + 3 < NC) stage(c + 3, As_u);
    };

    stage(0, sb);
    stage(1, sb + STG);
    stage(2, sb + 2 * STG);
    asm volatile("cp.async.wait_group 2;" ::: "memory");
    __syncthreads();

    if constexpr (NC <= 12) {
        #pragma unroll
        for (int c = 0; c < NC; ++c)
            chunk(c, sb + (c % 3) * STG);
    } else {
        #pragma unroll 6
        for (int c = 0; c < NC; ++c)
            chunk(c, sb + (c % 3) * STG);
    }

    float* ush = (float*)smem;
    if (EPI == 2) {
        for (int i = tid; i < 4096; i += 256) ush[i] = uw[i];
        for (int i = tid; i < 512; i += 256) ush[4096 + i] = bias[i] + ub[i];
        __syncthreads();
    }

    #pragma unroll
    for (int mf = 0; mf < 4; ++mf) {
        size_t row0 = (size_t)(cRow + wm * 64 + mf * 16 + g);
        size_t row1 = row0 + 8;
        float p0[8], p1[8];
        if (EPI == 2) {
            float4 a0 = *reinterpret_cast<const float4*>(cpre + row0 * 8);
            float4 a1 = *reinterpret_cast<const float4*>(cpre + row0 * 8 + 4);
            float4 b0 = *reinterpret_cast<const float4*>(cpre + row1 * 8);
            float4 b1 = *reinterpret_cast<const float4*>(cpre + row1 * 8 + 4);
            p0[0]=qgelu(a0.x); p0[1]=qgelu(a0.y); p0[2]=qgelu(a0.z); p0[3]=qgelu(a0.w);
            p0[4]=qgelu(a1.x); p0[5]=qgelu(a1.y); p0[6]=qgelu(a1.z); p0[7]=qgelu(a1.w);
            p1[0]=qgelu(b0.x); p1[1]=qgelu(b0.y); p1[2]=qgelu(b0.z); p1[3]=qgelu(b0.w);
            p1[4]=qgelu(b1.x); p1[5]=qgelu(b1.y); p1[6]=qgelu(b1.z); p1[7]=qgelu(b1.w);
        }
        #pragma unroll
        for (int nf = 0; nf < 4; ++nf) {
            int col = cCol + wn * 32 + nf * 8 + 2 * t;
            if (EPI == 0) {
                uint32_t* C = (uint32_t*)Cv;
                C[(row0 * N + col) >> 1] = pack_half(acc[mf][nf][0], acc[mf][nf][1]);
                C[(row1 * N + col) >> 1] = pack_half(acc[mf][nf][2], acc[mf][nf][3]);
            } else if (EPI == 1) {
                float b0 = bias[col], b1 = bias[col + 1];
                uint32_t* C = (uint32_t*)Cv;
                C[(row0 * N + col) >> 1] =
                    pack_half(gelu_exact(acc[mf][nf][0] + b0), gelu_exact(acc[mf][nf][1] + b1));
                C[(row1 * N + col) >> 1] =
                    pack_half(gelu_exact(acc[mf][nf][2] + b0), gelu_exact(acc[mf][nf][3] + b1));
            } else {
                float u0 = ush[4096 + col], u1 = ush[4096 + col + 1];
                float u2 = u0, u3 = u1;
                #pragma unroll
                for (int a = 0; a < 8; ++a) {
                    float w0 = ush[a * 512 + col], w1 = ush[a * 512 + col + 1];
                    u0 += p0[a] * w0; u1 += p0[a] * w1;
                    u2 += p1[a] * w0; u3 += p1[a] * w1;
                }
                float2 r0 = *reinterpret_cast<const float2*>(&res[row0 * N + col]);
                float2 r1 = *reinterpret_cast<const float2*>(&res[row1 * N + col]);
                float* C = (float*)Cv;
                *reinterpret_cast<float2*>(&C[row0 * N + col]) =
                    make_float2(acc[mf][nf][0] + u0 + r0.x, acc[mf][nf][1] + u1 + r0.y);
                *reinterpret_cast<float2*>(&C[row1 * N + col]) =
                    make_float2(acc[mf][nf][2] + u2 + r1.x, acc[mf][nf][3] + u3 + r1.y);
            }
        }
    }
}

// ---------------- fused flash attention (fp16 mma, log2-domain softmax) ------------
#define FH 72
#define FA_C 0.180336880f      // 0.125 * log2(e)
__global__ __launch_bounds__(256) void flash_attn_h(const __half* __restrict__ qkv,
                                                    __half* __restrict__ O) {
    __shared__ __half fb[2 * 128 * FH];
    const int tid = threadIdx.x;
    const int lane = tid & 31;
    const int w = tid >> 5;
    const int g = lane >> 2, t = lane & 3;
    const int qt = blockIdx.x;
    const int bhid = blockIdx.y;
    const int b = bhid >> 3, h = bhid & 7;
    const int r0 = w * 16 + g;

    const uint32_t fb_u = smem_u32(fb);
    const __half* qptr = qkv + ((size_t)b * NN + qt * 128) * 1536 + h * 64;

    // stage raw Q into buf0 (scale folded into log2-domain softmax)
    #pragma unroll
    for (int i = 0; i < 4; ++i) {
        int idx = tid + 256 * i;
        int r = idx >> 3, q = (idx & 7) * 8;
        *reinterpret_cast<uint4*>(fb + r * FH + q) =
            *reinterpret_cast<const uint4*>(qptr + (size_t)r * 1536 + q);
    }
    __syncthreads();
    uint32_t qf[4][4];
    {
        const uint32_t* Q2 = reinterpret_cast<const uint32_t*>(fb);
        #pragma unroll
        for (int ks = 0; ks < 4; ++ks) {
            int base = r0 * (FH / 2) + ks * 8 + t;
            qf[ks][0] = Q2[base];
            qf[ks][1] = Q2[base + 8 * (FH / 2)];
            qf[ks][2] = Q2[base + 4];
            qf[ks][3] = Q2[base + 8 * (FH / 2) + 4];
        }
    }
    __syncthreads();

    const __half* kptr = qkv + (size_t)b * NN * 1536 + 512 + h * 64;
    const __half* vptr = kptr + 512;
    const uint32_t kb_lane = ((uint32_t)((lane & 7) + ((lane & 16) ? 8 : 0)) * FH
                             + ((lane & 8) ? 8 : 0)) * 2;

    float oacc[8][4] = {};
    // m tracked in raw-score units; exponentials evaluated in log2 domain via C.
    float m0 = -1e30f, m1 = -1e30f, l0 = 0.f, l1 = 0.f;

    for (int kt = 0; kt < 8; ++kt) {
        const uint32_t base_u = fb_u + (uint32_t)((kt & 1) * 128 * FH) * 2;
        __half* Kb = fb + (kt & 1) * 128 * FH;
        #pragma unroll
        for (int i = 0; i < 2; ++i) {
            int idx = tid + 256 * i;
            int r = idx >> 3, q = (idx & 7) * 8;
            size_t off = (size_t)(kt * 64 + r) * 1536 + q;
            *reinterpret_cast<uint4*>(Kb + r * FH + q) =
                *reinterpret_cast<const uint4*>(kptr + off);
            *reinterpret_cast<uint4*>(Kb + (64 + r) * FH + q) =
                *reinterpret_cast<const uint4*>(vptr + off);
        }
        __syncthreads();

        float sacc[8][4] = {};
        #pragma unroll
        for (int ks = 0; ks < 4; ++ks) {
            #pragma unroll
            for (int p = 0; p < 4; ++p) {
                uint32_t r0v, r1v, r2v, r3v;
                uint32_t addr = base_u + kb_lane +
                    ((uint32_t)(p * 16 * FH + ks * 16) << 1);
                LDSM_X4(r0v, r1v, r2v, r3v, addr);
                uint32_t b0[2] = {r0v, r1v}, b1[2] = {r2v, r3v};
                mma_fp16(sacc[2 * p],     qf[ks], b0);
                mma_fp16(sacc[2 * p + 1], qf[ks], b1);
            }
        }
        float mx0 = -1e30f, mx1 = -1e30f;
        #pragma unroll
        for (int nf = 0; nf < 8; ++nf) {
            mx0 = fmaxf(mx0, fmaxf(sacc[nf][0], sacc[nf][1]));
            mx1 = fmaxf(mx1, fmaxf(sacc[nf][2], sacc[nf][3]));
        }
        mx0 = fmaxf(mx0, __shfl_xor_sync(0xffffffffu, mx0, 1));
        mx0 = fmaxf(mx0, __shfl_xor_sync(0xffffffffu, mx0, 2));
        mx1 = fmaxf(mx1, __shfl_xor_sync(0xffffffffu, mx1, 1));
        mx1 = fmaxf(mx1, __shfl_xor_sync(0xffffffffu, mx1, 2));
        float mn0 = fmaxf(m0, mx0), mn1 = fmaxf(m1, mx1);
        float f0 = ex2((m0 - mn0) * FA_C), f1 = ex2((m1 - mn1) * FA_C);
        m0 = mn0; m1 = mn1;
        float nc0 = -mn0 * FA_C, nc1 = -mn1 * FA_C;
        float rs0 = 0.f, rs1 = 0.f;
        #pragma unroll
        for (int nf = 0; nf < 8; ++nf) {
            sacc[nf][0] = ex2(fmaf(sacc[nf][0], FA_C, nc0));
            sacc[nf][1] = ex2(fmaf(sacc[nf][1], FA_C, nc0));
            sacc[nf][2] = ex2(fmaf(sacc[nf][2], FA_C, nc1));
            sacc[nf][3] = ex2(fmaf(sacc[nf][3], FA_C, nc1));
            rs0 += sacc[nf][0] + sacc[nf][1];
            rs1 += sacc[nf][2] + sacc[nf][3];
        }
        rs0 += __shfl_xor_sync(0xffffffffu, rs0, 1);
        rs0 += __shfl_xor_sync(0xffffffffu, rs0, 2);
        rs1 += __shfl_xor_sync(0xffffffffu, rs1, 1);
        rs1 += __shfl_xor_sync(0xffffffffu, rs1, 2);
        l0 = l0 * f0 + rs0; l1 = l1 * f1 + rs1;
        #pragma unroll
        for (int nf = 0; nf < 8; ++nf) {
            oacc[nf][0] *= f0; oacc[nf][1] *= f0;
            oacc[nf][2] *= f1; oacc[nf][3] *= f1;
        }
        const uint32_t vs_u = base_u + (uint32_t)(64 * FH) * 2;
        #pragma unroll
        for (int ks = 0; ks < 4; ++ks) {
            uint32_t af[4] = {
                pack_half(sacc[2 * ks][0],     sacc[2 * ks][1]),
                pack_half(sacc[2 * ks][2],     sacc[2 * ks][3]),
                pack_half(sacc[2 * ks + 1][0], sacc[2 * ks + 1][1]),
                pack_half(sacc[2 * ks + 1][2], sacc[2 * ks + 1][3])};
            #pragma unroll
            for (int p = 0; p < 4; ++p) {
                uint32_t r0v, r1v, r2v, r3v;
                uint32_t addr = vs_u +
                    ((uint32_t)((16 * ks + (lane & 7) + ((lane & 8) ? 8 : 0)) * FH
                                + p * 16 + ((lane & 16) ? 8 : 0)) << 1);
                LDSM_X4_T(r0v, r1v, r2v, r3v, addr);
                uint32_t b0[2] = {r0v, r1v}, b1[2] = {r2v, r3v};
                mma_fp16(oacc[2 * p],     af, b0);
                mma_fp16(oacc[2 * p + 1], af, b1);
            }
        }
    }

    float i0 = 1.0f / l0, i1 = 1.0f / l1;
    size_t orow = (size_t)(b * NN + qt * 128 + r0);
    uint32_t* O2 = reinterpret_cast<uint32_t*>(O);
    #pragma unroll
    for (int nf = 0; nf < 8; ++nf) {
        int col = h * 64 + nf * 8 + 2 * t;
        O2[(orow * CC + col) >> 1]       = pack_half(oacc[nf][0] * i0, oacc[nf][1] * i0);
        O2[((orow + 8) * CC + col) >> 1] = pack_half(oacc[nf][2] * i1, oacc[nf][3] * i1);
    }
}

// ---------------- 3D conv, z-slice blocks with SMEM halo ----------------
__global__ __launch_bounds__(256) void conv3d_z(const float* __restrict__ din,
                                                const float* __restrict__ cw,
                                                const float* __restrict__ cb,
                                                float* __restrict__ out) {
    __shared__ float ds[3][64][8];
    __shared__ float w[1728];
    __shared__ float bsh[8];
    const int zz = blockIdx.x;
    const int b = blockIdx.y;
    const int tid = threadIdx.x;

    for (int i = tid; i < 1728; i += 256) w[i] = cw[i];
    if (tid < 8) bsh[tid] = cb[tid];
    #pragma unroll
    for (int i = 0; i < 6; ++i) {
        int idx = tid + 256 * i;
        int dz = idx >> 9;
        int sp = (idx >> 3) & 63;
        int ch = idx & 7;
        int z = zz + dz - 1;
        float v = 0.f;
        if ((unsigned)z <= 7u)
            v = din[((size_t)b * 512 + z * 64 + sp) * 8 + ch];
        ds[dz][sp][ch] = v;
    }
    __syncthreads();

    #pragma unroll
    for (int it = 0; it < 2; ++it) {
        int idx = tid + 256 * it;
        int o = idx & 7;
        int sp = idx >> 3;
        int xx = sp & 7, yy = sp >> 3;
        float acc = bsh[o];
        #pragma unroll
        for (int dz = 0; dz < 3; ++dz) {
            #pragma unroll
            for (int dy = -1; dy <= 1; ++dy) {
                int y = yy + dy; if ((unsigned)y > 7u) continue;
                #pragma unroll
                for (int dx = -1; dx <= 1; ++dx) {
                    int xc = xx + dx; if ((unsigned)xc > 7u) continue;
                    const float* ip = ds[dz][y * 8 + xc];
                    const float* wp = w + o * 216 + (dz * 3 + (dy + 1)) * 3 + (dx + 1);
                    #pragma unroll
                    for (int i = 0; i < 8; ++i) acc += ip[i] * wp[i * 27];
                }
            }
        }
        out[((size_t)b * 512 + zz * 64 + sp) * 8 + o] = acc;
    }
}

// ---------------- launcher ----------------
static float* symaddr(const void* sym) {
    void* p = nullptr;
    cudaGetSymbolAddress(&p, sym);
    return (float*)p;
}

extern "C" void kernel_launch(void* const* d_in, const int* in_sizes, int n_in,
                              void* d_out, int out_size) {
    (void)in_sizes; (void)n_in; (void)out_size;
    const float* x      = (const float*)d_in[0];
    const float* pos    = (const float*)d_in[1];
    const float* ln1_g  = (const float*)d_in[2];
    const float* ln1_b  = (const float*)d_in[3];
    const float* qkv_w  = (const float*)d_in[4];
    const float* proj_w = (const float*)d_in[5];
    const float* proj_b = (const float*)d_in[6];
    const float* cp1_dw = (const float*)d_in[7];
    const float* cp1_db = (const float*)d_in[8];
    const float* cp1_cw = (const float*)d_in[9];
    const float* cp1_cb = (const float*)d_in[10];
    const float* cp1_uw = (const float*)d_in[11];
    const float* cp1_ub = (const float*)d_in[12];
    const float* ln2_g  = (const float*)d_in[13];
    const float* ln2_b  = (const float*)d_in[14];
    const float* ff_w1  = (const float*)d_in[15];
    const float* ff_b1  = (const float*)d_in[16];
    const float* ff_w2  = (const float*)d_in[17];
    const float* ff_b2  = (const float*)d_in[18];
    const float* cp2_dw = (const float*)d_in[19];
    const float* cp2_db = (const float*)d_in[20];
    const float* cp2_cw = (const float*)d_in[21];
    const float* cp2_cb = (const float*)d_in[22];
    const float* cp2_uw = (const float*)d_in[23];
    const float* cp2_ub = (const float*)d_in[24];
    float* out = (float*)d_out;

    float*  bx    = symaddr(g_x);
    __half* bh    = (__half*)symaddr(g_h);
    __half* bhb   = (__half*)symaddr(g_hb);
    __half* bqkv  = (__half*)symaddr(g_qkv);
    __half* bao   = (__half*)symaddr(g_ao);
    __half* bmlp  = (__half*)symaddr(g_mlp);
    float*  bd    = symaddr(g_d);
    float*  bc    = symaddr(g_c);
    __half* wqkvT = (__half*)symaddr(g_wqkvT);
    __half* wprojT= (__half*)symaddr(g_wprojT);
    __half* wff1T = (__half*)symaddr(g_wff1T);
    __half* wff2T = (__half*)symaddr(g_wff2T);

    cudaFuncSetAttribute(tc_gemm16<0,8>,  cudaFuncAttributeMaxDynamicSharedMemorySize, GEMM_SMEM);
    cudaFuncSetAttribute(tc_gemm16<1,8>,  cudaFuncAttributeMaxDynamicSharedMemorySize, GEMM_SMEM);
    cudaFuncSetAttribute(tc_gemm16<2,8>,  cudaFuncAttributeMaxDynamicSharedMemorySize, GEMM_SMEM);
    cudaFuncSetAttribute(tc_gemm16<2,64>, cudaFuncAttributeMaxDynamicSharedMemorySize, GEMM_SMEM);

    // all weight transposes in one launch
    transpose_all<<<5120, dim3(32, 8)>>>(qkv_w, wqkvT, proj_w, wprojT,
                                         ff_w1, wff1T, ff_w2, wff2T);

    // x = x + pos ; h = LN1(x) -> fp16 ; d1 = qgelu(h@dw1+db1)
    add_ln_down<<<MROWS, 256>>>(x, pos, ln1_g, ln1_b, cp1_dw, cp1_db, bx, bh, bd);
    conv3d_z<<<dim3(8, BB), 256>>>(bd, cp1_cw, cp1_cb, bc);

    // qkv = h @ qkv_w -> fp16   (K=512 -> NC=8)
    tc_gemm16<0,8><<<dim3(12, 128), 256, GEMM_SMEM>>>(bh, wqkvT, nullptr, bqkv,
                                                      MROWS, 3 * CC, CC,
                                                      nullptr, nullptr, nullptr, nullptr);
    // fused fp16 flash attention -> fp16
    flash_attn_h<<<dim3(4, BB * HH), 256>>>(bqkv, bao);

    // proj fused: x = x + (ao@projW + proj_b) + up1(qgelu(conv1)) + cp1_ub
    tc_gemm16<2,8><<<dim3(4, 128), 256, GEMM_SMEM>>>(bao, wprojT, proj_b, bx,
                                                     MROWS, CC, CC,
                                                     bx, bc, cp1_uw, cp1_ub);

    // h2 = LN2(x) -> fp16 ; d2 = qgelu(h2@dw2+db2)
    ln_h_down<<<MROWS, 256>>>(bx, ln2_g, ln2_b, cp2_dw, cp2_db, bhb, bd);
    conv3d_z<<<dim3(8, BB), 256>>>(bd, cp2_cw, cp2_cb, bc);

    // FFN fp16
    tc_gemm16<1,8><<<dim3(32, 128), 256, GEMM_SMEM>>>(bhb, wff1T, ff_b1, bmlp,
                                                      MROWS, MLPD, CC,
                                                      nullptr, nullptr, nullptr, nullptr);
    tc_gemm16<2,64><<<dim3(4, 128), 256, GEMM_SMEM>>>(bmlp, wff2T, ff_b2, out,
                                                      MROWS, CC, MLPD,
                                                      bx, bc, cp2_uw, cp2_ub);
}

// round 16
// speedup vs baseline: 1.0221x; 1.0221x over previous
#include <cuda_runtime.h>
#include <cuda_fp16.h>
#include <cstdint>

// ---------------- problem constants ----------------
#define BB    32
#define NN    512
#define CC    512
#define HH    8
#define DHD   64
#define ADIM  8
#define MLPD  4096
#define MROWS (BB*NN)          // 16384

// ---------------- static device scratch ----------------
__device__ __align__(16) float  g_x  [(size_t)MROWS*CC];
__device__ __align__(16) __half g_h  [(size_t)MROWS*CC];
__device__ __align__(16) __half g_hb [(size_t)MROWS*CC];
__device__ __align__(16) __half g_qkv[(size_t)MROWS*3*CC];
__device__ __align__(16) __half g_ao [(size_t)MROWS*CC];
__device__ __align__(16) __half g_mlp[(size_t)MROWS*MLPD];
__device__ __align__(16) float  g_d  [(size_t)MROWS*ADIM];
__device__ __align__(16) float  g_c  [(size_t)MROWS*ADIM];
__device__ __align__(16) __half g_wqkvT[(size_t)3*CC*CC];
__device__ __align__(16) __half g_wprojT[(size_t)CC*CC];
__device__ __align__(16) __half g_wff1T[(size_t)MLPD*CC];
__device__ __align__(16) __half g_wff2T[(size_t)CC*MLPD];

// ---------------- helpers ----------------
__device__ __forceinline__ float qgelu(float v) { return v / (1.0f + __expf(-1.702f * v)); }
__device__ __forceinline__ float gelu_exact(float v) { return 0.5f * v * (1.0f + erff(v * 0.70710678118654752f)); }
__device__ __forceinline__ float ex2(float x) {
    float r; asm("ex2.approx.f32 %0, %1;" : "=f"(r) : "f"(x)); return r;
}
__device__ __forceinline__ uint32_t smem_u32(const void* p) {
    uint32_t a;
    asm("{ .reg .u64 t; cvta.to.shared.u64 t, %1; cvt.u32.u64 %0, t; }" : "=r"(a) : "l"(p));
    return a;
}
__device__ __forceinline__ void cp16(uint32_t saddr, const void* g) {
    asm volatile("cp.async.cg.shared.global [%0], [%1], 16;" :: "r"(saddr), "l"(g));
}
__device__ __forceinline__ void mma_fp16(float d[4], const uint32_t a[4], const uint32_t b[2]) {
    asm volatile("mma.sync.aligned.m16n8k16.row.col.f32.f16.f16.f32 "
        "{%0,%1,%2,%3}, {%4,%5,%6,%7}, {%8,%9}, {%0,%1,%2,%3};"
        : "+f"(d[0]), "+f"(d[1]), "+f"(d[2]), "+f"(d[3])
        : "r"(a[0]), "r"(a[1]), "r"(a[2]), "r"(a[3]), "r"(b[0]), "r"(b[1]));
}
#define LDSM_X4(r0, r1, r2, r3, addr) \
    asm volatile("ldmatrix.sync.aligned.m8n8.x4.shared.b16 {%0,%1,%2,%3}, [%4];" \
        : "=r"(r0), "=r"(r1), "=r"(r2), "=r"(r3) : "r"(addr))
#define LDSM_X4_T(r0, r1, r2, r3, addr) \
    asm volatile("ldmatrix.sync.aligned.m8n8.x4.trans.shared.b16 {%0,%1,%2,%3}, [%4];" \
        : "=r"(r0), "=r"(r1), "=r"(r2), "=r"(r3) : "r"(addr))
__device__ __forceinline__ uint32_t pack_half(float a, float b) {
    __half2 v = __floats2half2_rn(a, b);
    return *reinterpret_cast<uint32_t*>(&v);
}

__device__ __forceinline__ float blockReduceSum256(float v) {
    __shared__ float sh[8];
    int lane = threadIdx.x & 31, w = threadIdx.x >> 5;
    #pragma unroll
    for (int o = 16; o > 0; o >>= 1) v += __shfl_down_sync(0xffffffffu, v, o);
    if (lane == 0) sh[w] = v;
    __syncthreads();
    if (threadIdx.x < 8) {
        float t = sh[threadIdx.x];
        t += __shfl_down_sync(0xffu, t, 4);
        t += __shfl_down_sync(0xffu, t, 2);
        t += __shfl_down_sync(0xffu, t, 1);
        if (threadIdx.x == 0) sh[0] = t;
    }
    __syncthreads();
    float r = sh[0];
    __syncthreads();
    return r;
}

__device__ __forceinline__ void downReduceStore(float p[8], const float* __restrict__ db,
                                                float* __restrict__ dout, size_t row) {
    __shared__ float sh8[8][8];
    int lane = threadIdx.x & 31, w = threadIdx.x >> 5;
    #pragma unroll
    for (int a = 0; a < 8; ++a) {
        #pragma unroll
        for (int o = 16; o > 0; o >>= 1)
            p[a] += __shfl_down_sync(0xffffffffu, p[a], o);
    }
    if (lane == 0) {
        #pragma unroll
        for (int a = 0; a < 8; ++a) sh8[w][a] = p[a];
    }
    __syncthreads();
    if (threadIdx.x < 8) {
        float s = 0.f;
        #pragma unroll
        for (int ww = 0; ww < 8; ++ww) s += sh8[ww][threadIdx.x];
        dout[row * 8 + threadIdx.x] = qgelu(s + db[threadIdx.x]);
    }
}

// ---------------- fused (x+pos) + LN1 -> fp16 + adapter-down ----------------
__global__ __launch_bounds__(256) void add_ln_down(const float* __restrict__ xin,
                                                   const float* __restrict__ pos,
                                                   const float* __restrict__ g,
                                                   const float* __restrict__ b,
                                                   const float* __restrict__ dw,
                                                   const float* __restrict__ db,
                                                   float* __restrict__ xout,
                                                   __half* __restrict__ hout,
                                                   float* __restrict__ dout) {
    size_t row = blockIdx.x;
    int tid = threadIdx.x;
    float v0 = xin[row * CC + tid]       + pos[row * CC + tid];
    float v1 = xin[row * CC + tid + 256] + pos[row * CC + tid + 256];
    xout[row * CC + tid]       = v0;
    xout[row * CC + tid + 256] = v1;
    float mean = blockReduceSum256(v0 + v1) * (1.0f / 512.0f);
    float d0 = v0 - mean, d1 = v1 - mean;
    float var = blockReduceSum256(d0 * d0 + d1 * d1) * (1.0f / 512.0f);
    float inv = rsqrtf(var + 1e-5f);
    float h0 = d0 * inv * g[tid]       + b[tid];
    float h1 = d1 * inv * g[tid + 256] + b[tid + 256];
    hout[row * CC + tid]       = __float2half_rn(h0);
    hout[row * CC + tid + 256] = __float2half_rn(h1);
    float4 wA0 = *reinterpret_cast<const float4*>(dw + tid * 8);
    float4 wA1 = *reinterpret_cast<const float4*>(dw + tid * 8 + 4);
    float4 wB0 = *reinterpret_cast<const float4*>(dw + (tid + 256) * 8);
    float4 wB1 = *reinterpret_cast<const float4*>(dw + (tid + 256) * 8 + 4);
    float p[8];
    p[0] = h0 * wA0.x + h1 * wB0.x; p[1] = h0 * wA0.y + h1 * wB0.y;
    p[2] = h0 * wA0.z + h1 * wB0.z; p[3] = h0 * wA0.w + h1 * wB0.w;
    p[4] = h0 * wA1.x + h1 * wB1.x; p[5] = h0 * wA1.y + h1 * wB1.y;
    p[6] = h0 * wA1.z + h1 * wB1.z; p[7] = h0 * wA1.w + h1 * wB1.w;
    downReduceStore(p, db, dout, row);
}

// ---------------- LN2 + adapter-down ----------------
__global__ __launch_bounds__(256) void ln_h_down(const float* __restrict__ in,
                                                 const float* __restrict__ g,
                                                 const float* __restrict__ b,
                                                 const float* __restrict__ dw,
                                                 const float* __restrict__ db,
                                                 __half* __restrict__ out,
                                                 float* __restrict__ dout) {
    size_t row = blockIdx.x;
    int tid = threadIdx.x;
    float v0 = in[row * CC + tid], v1 = in[row * CC + tid + 256];
    float mean = blockReduceSum256(v0 + v1) * (1.0f / 512.0f);
    float d0 = v0 - mean, d1 = v1 - mean;
    float var = blockReduceSum256(d0 * d0 + d1 * d1) * (1.0f / 512.0f);
    float inv = rsqrtf(var + 1e-5f);
    float h0 = d0 * inv * g[tid]       + b[tid];
    float h1 = d1 * inv * g[tid + 256] + b[tid + 256];
    out[row * CC + tid]       = __float2half_rn(h0);
    out[row * CC + tid + 256] = __float2half_rn(h1);
    float4 wA0 = *reinterpret_cast<const float4*>(dw + tid * 8);
    float4 wA1 = *reinterpret_cast<const float4*>(dw + tid * 8 + 4);
    float4 wB0 = *reinterpret_cast<const float4*>(dw + (tid + 256) * 8);
    float4 wB1 = *reinterpret_cast<const float4*>(dw + (tid + 256) * 8 + 4);
    float p[8];
    p[0] = h0 * wA0.x + h1 * wB0.x; p[1] = h0 * wA0.y + h1 * wB0.y;
    p[2] = h0 * wA0.z + h1 * wB0.z; p[3] = h0 * wA0.w + h1 * wB0.w;
    p[4] = h0 * wA1.x + h1 * wB1.x; p[5] = h0 * wA1.y + h1 * wB1.y;
    p[6] = h0 * wA1.z + h1 * wB1.z; p[7] = h0 * wA1.w + h1 * wB1.w;
    downReduceStore(p, db, dout, row);
}

// ---------------- merged weight transpose ----------------
__global__ void transpose_all(const float* __restrict__ w0, __half* __restrict__ o0,
                              const float* __restrict__ w1, __half* __restrict__ o1,
                              const float* __restrict__ w2, __half* __restrict__ o2,
                              const float* __restrict__ w3, __half* __restrict__ o3) {
    __shared__ float t[32][33];
    int bid = blockIdx.x;
    const float* in; __half* out; int R, Cc, tx, ty;
    if (bid < 768)        { in = w0; out = o0; R = 512;  Cc = 1536; int l = bid;        tx = l % 48;  ty = l / 48; }
    else if (bid < 1024)  { in = w1; out = o1; R = 512;  Cc = 512;  int l = bid - 768;  tx = l % 16;  ty = l / 16; }
    else if (bid < 3072)  { in = w2; out = o2; R = 512;  Cc = 4096; int l = bid - 1024; tx = l % 128; ty = l / 128; }
    else                  { in = w3; out = o3; R = 4096; Cc = 512;  int l = bid - 3072; tx = l % 16;  ty = l / 16; }
    int bx = tx * 32, by = ty * 32;
    #pragma unroll
    for (int i = 0; i < 32; i += 8)
        t[threadIdx.y + i][threadIdx.x] = in[(size_t)(by + threadIdx.y + i) * Cc + bx + threadIdx.x];
    __syncthreads();
    #pragma unroll
    for (int i = 0; i < 32; i += 8)
        out[(size_t)(bx + threadIdx.y + i) * R + by + threadIdx.x] =
            __float2half_rn(t[threadIdx.x][threadIdx.y + i]);
}

// ---------------- fp16 mma GEMM, 256 thr, warp tile 64x32, templated NC -----------
// Full unroll for all NC (R13/R14-proven; partial unroll regressed in R15).
#define STG 32768
#define GEMM_SMEM (3*STG)      // 98304
template<int EPI, int NC>
__global__ __launch_bounds__(256, 2) void tc_gemm16(const __half* __restrict__ A,
                                                    const __half* __restrict__ BT,
                                                    const float* __restrict__ bias,
                                                    void* __restrict__ Cv,
                                                    int M, int N, int K,
                                                    const float* __restrict__ res,
                                                    const float* __restrict__ cpre,
                                                    const float* __restrict__ uw,
                                                    const float* __restrict__ ub) {
    extern __shared__ char smem[];
    const uint32_t sb = smem_u32(smem);
    const int tid = threadIdx.x;
    const int lane = tid & 31;
    const int w = tid >> 5;
    const int wm = w & 1, wn = w >> 1;
    const int g = lane >> 2, t = lane & 3;
    const int cRow = blockIdx.y * 128;
    const int cCol = blockIdx.x * 128;

    const int r_st = tid >> 3;
    const int j_st = tid & 7;

    const int rb = lane & 7;
    const int a_row = wm * 64 + (lane & 15);
    const int a_j0  = lane >> 4;
    const int b_row = wn * 32 + (lane & 7) + ((lane & 16) ? 8 : 0);
    const int b_j0  = (lane >> 3) & 1;

    float acc[4][4][4] = {};

    auto stage = [&](int kt, uint32_t abase) {
        const int k0 = kt << 6;
        const uint32_t bbase = abase + 16384;
        #pragma unroll
        for (int i = 0; i < 4; ++i) {
            int r = r_st + i * 32;
            uint32_t phys = (uint32_t)r * 128 + ((uint32_t)(j_st ^ (r & 7)) << 4);
            cp16(abase + phys, A + (size_t)(cRow + r) * K + k0 + j_st * 8);
            cp16(bbase + phys, BT + (size_t)(cCol + r) * K + k0 + j_st * 8);
        }
        asm volatile("cp.async.commit_group;" ::: "memory");
    };

    stage(0, sb);
    stage(1, sb + STG);
    stage(2, sb + 2 * STG);
    asm volatile("cp.async.wait_group 2;" ::: "memory");
    __syncthreads();

    #pragma unroll
    for (int c = 0; c < NC; ++c) {
        const int s = c % 3;
        const uint32_t As_u = sb + s * STG;
        const uint32_t Bs_u = As_u + 16384;
        #pragma unroll
        for (int ks = 0; ks < 4; ++ks) {
            uint32_t af[4][4], bf[4][2];
            #pragma unroll
            for (int mf = 0; mf < 4; ++mf) {
                int row = a_row + mf * 16;
                uint32_t addr = As_u + (uint32_t)row * 128 +
                                ((uint32_t)((a_j0 + 2 * ks) ^ rb) << 4);
                LDSM_X4(af[mf][0], af[mf][1], af[mf][2], af[mf][3], addr);
            }
            #pragma unroll
            for (int p = 0; p < 2; ++p) {
                int row = b_row + p * 16;
                uint32_t addr = Bs_u + (uint32_t)row * 128 +
                                ((uint32_t)((b_j0 + 2 * ks) ^ rb) << 4);
                uint32_t r0, r1, r2, r3;
                LDSM_X4(r0, r1, r2, r3, addr);
                bf[2 * p][0] = r0; bf[2 * p][1] = r1;
                bf[2 * p + 1][0] = r2; bf[2 * p + 1][1] = r3;
            }
            #pragma unroll
            for (int mf = 0; mf < 4; ++mf)
                #pragma unroll
                for (int nf = 0; nf < 4; ++nf)
                    mma_fp16(acc[mf][nf], af[mf], bf[nf]);
        }
        if (c + 2 < NC)      { asm volatile("cp.async.wait_group 1;" ::: "memory"); }
        else if (c + 1 < NC) { asm volatile("cp.async.wait_group 0;" ::: "memory"); }
        __syncthreads();
        if (c + 3 < NC) stage(c + 3, As_u);
    }

    float* ush = (float*)smem;
    if (EPI == 2) {
        for (int i = tid; i < 4096; i += 256) ush[i] = uw[i];
        for (int i = tid; i < 512; i += 256) ush[4096 + i] = bias[i] + ub[i];
        __syncthreads();
    }

    #pragma unroll
    for (int mf = 0; mf < 4; ++mf) {
        size_t row0 = (size_t)(cRow + wm * 64 + mf * 16 + g);
        size_t row1 = row0 + 8;
        float p0[8], p1[8];
        if (EPI == 2) {
            float4 a0 = *reinterpret_cast<const float4*>(cpre + row0 * 8);
            float4 a1 = *reinterpret_cast<const float4*>(cpre + row0 * 8 + 4);
            float4 b0 = *reinterpret_cast<const float4*>(cpre + row1 * 8);
            float4 b1 = *reinterpret_cast<const float4*>(cpre + row1 * 8 + 4);
            p0[0]=qgelu(a0.x); p0[1]=qgelu(a0.y); p0[2]=qgelu(a0.z); p0[3]=qgelu(a0.w);
            p0[4]=qgelu(a1.x); p0[5]=qgelu(a1.y); p0[6]=qgelu(a1.z); p0[7]=qgelu(a1.w);
            p1[0]=qgelu(b0.x); p1[1]=qgelu(b0.y); p1[2]=qgelu(b0.z); p1[3]=qgelu(b0.w);
            p1[4]=qgelu(b1.x); p1[5]=qgelu(b1.y); p1[6]=qgelu(b1.z); p1[7]=qgelu(b1.w);
        }
        #pragma unroll
        for (int nf = 0; nf < 4; ++nf) {
            int col = cCol + wn * 32 + nf * 8 + 2 * t;
            if (EPI == 0) {
                uint32_t* C = (uint32_t*)Cv;
                C[(row0 * N + col) >> 1] = pack_half(acc[mf][nf][0], acc[mf][nf][1]);
                C[(row1 * N + col) >> 1] = pack_half(acc[mf][nf][2], acc[mf][nf][3]);
            } else if (EPI == 1) {
                float b0 = bias[col], b1 = bias[col + 1];
                uint32_t* C = (uint32_t*)Cv;
                C[(row0 * N + col) >> 1] =
                    pack_half(gelu_exact(acc[mf][nf][0] + b0), gelu_exact(acc[mf][nf][1] + b1));
                C[(row1 * N + col) >> 1] =
                    pack_half(gelu_exact(acc[mf][nf][2] + b0), gelu_exact(acc[mf][nf][3] + b1));
            } else {
                float u0 = ush[4096 + col], u1 = ush[4096 + col + 1];
                float u2 = u0, u3 = u1;
                #pragma unroll
                for (int a = 0; a < 8; ++a) {
                    float w0 = ush[a * 512 + col], w1 = ush[a * 512 + col + 1];
                    u0 += p0[a] * w0; u1 += p0[a] * w1;
                    u2 += p1[a] * w0; u3 += p1[a] * w1;
                }
                float2 r0 = *reinterpret_cast<const float2*>(&res[row0 * N + col]);
                float2 r1 = *reinterpret_cast<const float2*>(&res[row1 * N + col]);
                float* C = (float*)Cv;
                *reinterpret_cast<float2*>(&C[row0 * N + col]) =
                    make_float2(acc[mf][nf][0] + u0 + r0.x, acc[mf][nf][1] + u1 + r0.y);
                *reinterpret_cast<float2*>(&C[row1 * N + col]) =
                    make_float2(acc[mf][nf][2] + u2 + r1.x, acc[mf][nf][3] + u3 + r1.y);
            }
        }
    }
}

// ---------------- fused flash attention (fp16 mma, log2-domain softmax) ------------
#define FH 72
#define FA_C 0.180336880f      // 0.125 * log2(e)
__global__ __launch_bounds__(256) void flash_attn_h(const __half* __restrict__ qkv,
                                                    __half* __restrict__ O) {
    __shared__ __half fb[2 * 128 * FH];
    const int tid = threadIdx.x;
    const int lane = tid & 31;
    const int w = tid >> 5;
    const int g = lane >> 2, t = lane & 3;
    const int qt = blockIdx.x;
    const int bhid = blockIdx.y;
    const int b = bhid >> 3, h = bhid & 7;
    const int r0 = w * 16 + g;

    const uint32_t fb_u = smem_u32(fb);
    const __half* qptr = qkv + ((size_t)b * NN + qt * 128) * 1536 + h * 64;

    // stage raw Q into buf0 (scale folded into log2-domain softmax)
    #pragma unroll
    for (int i = 0; i < 4; ++i) {
        int idx = tid + 256 * i;
        int r = idx >> 3, q = (idx & 7) * 8;
        *reinterpret_cast<uint4*>(fb + r * FH + q) =
            *reinterpret_cast<const uint4*>(qptr + (size_t)r * 1536 + q);
    }
    __syncthreads();
    uint32_t qf[4][4];
    {
        const uint32_t* Q2 = reinterpret_cast<const uint32_t*>(fb);
        #pragma unroll
        for (int ks = 0; ks < 4; ++ks) {
            int base = r0 * (FH / 2) + ks * 8 + t;
            qf[ks][0] = Q2[base];
            qf[ks][1] = Q2[base + 8 * (FH / 2)];
            qf[ks][2] = Q2[base + 4];
            qf[ks][3] = Q2[base + 8 * (FH / 2) + 4];
        }
    }
    __syncthreads();

    const __half* kptr = qkv + (size_t)b * NN * 1536 + 512 + h * 64;
    const __half* vptr = kptr + 512;
    const uint32_t kb_lane = ((uint32_t)((lane & 7) + ((lane & 16) ? 8 : 0)) * FH
                             + ((lane & 8) ? 8 : 0)) * 2;

    float oacc[8][4] = {};
    float m0 = -1e30f, m1 = -1e30f, l0 = 0.f, l1 = 0.f;

    for (int kt = 0; kt < 8; ++kt) {
        const uint32_t base_u = fb_u + (uint32_t)((kt & 1) * 128 * FH) * 2;
        __half* Kb = fb + (kt & 1) * 128 * FH;
        #pragma unroll
        for (int i = 0; i < 2; ++i) {
            int idx = tid + 256 * i;
            int r = idx >> 3, q = (idx & 7) * 8;
            size_t off = (size_t)(kt * 64 + r) * 1536 + q;
            *reinterpret_cast<uint4*>(Kb + r * FH + q) =
                *reinterpret_cast<const uint4*>(kptr + off);
            *reinterpret_cast<uint4*>(Kb + (64 + r) * FH + q) =
                *reinterpret_cast<const uint4*>(vptr + off);
        }
        __syncthreads();

        float sacc[8][4] = {};
        #pragma unroll
        for (int ks = 0; ks < 4; ++ks) {
            #pragma unroll
            for (int p = 0; p < 4; ++p) {
                uint32_t r0v, r1v, r2v, r3v;
                uint32_t addr = base_u + kb_lane +
                    ((uint32_t)(p * 16 * FH + ks * 16) << 1);
                LDSM_X4(r0v, r1v, r2v, r3v, addr);
                uint32_t b0[2] = {r0v, r1v}, b1[2] = {r2v, r3v};
                mma_fp16(sacc[2 * p],     qf[ks], b0);
                mma_fp16(sacc[2 * p + 1], qf[ks], b1);
            }
        }
        float mx0 = -1e30f, mx1 = -1e30f;
        #pragma unroll
        for (int nf = 0; nf < 8; ++nf) {
            mx0 = fmaxf(mx0, fmaxf(sacc[nf][0], sacc[nf][1]));
            mx1 = fmaxf(mx1, fmaxf(sacc[nf][2], sacc[nf][3]));
        }
        mx0 = fmaxf(mx0, __shfl_xor_sync(0xffffffffu, mx0, 1));
        mx0 = fmaxf(mx0, __shfl_xor_sync(0xffffffffu, mx0, 2));
        mx1 = fmaxf(mx1, __shfl_xor_sync(0xffffffffu, mx1, 1));
        mx1 = fmaxf(mx1, __shfl_xor_sync(0xffffffffu, mx1, 2));
        float mn0 = fmaxf(m0, mx0), mn1 = fmaxf(m1, mx1);
        float f0 = ex2((m0 - mn0) * FA_C), f1 = ex2((m1 - mn1) * FA_C);
        m0 = mn0; m1 = mn1;
        float nc0 = -mn0 * FA_C, nc1 = -mn1 * FA_C;
        float rs0 = 0.f, rs1 = 0.f;
        #pragma unroll
        for (int nf = 0; nf < 8; ++nf) {
            sacc[nf][0] = ex2(fmaf(sacc[nf][0], FA_C, nc0));
            sacc[nf][1] = ex2(fmaf(sacc[nf][1], FA_C, nc0));
            sacc[nf][2] = ex2(fmaf(sacc[nf][2], FA_C, nc1));
            sacc[nf][3] = ex2(fmaf(sacc[nf][3], FA_C, nc1));
            rs0 += sacc[nf][0] + sacc[nf][1];
            rs1 += sacc[nf][2] + sacc[nf][3];
        }
        rs0 += __shfl_xor_sync(0xffffffffu, rs0, 1);
        rs0 += __shfl_xor_sync(0xffffffffu, rs0, 2);
        rs1 += __shfl_xor_sync(0xffffffffu, rs1, 1);
        rs1 += __shfl_xor_sync(0xffffffffu, rs1, 2);
        l0 = l0 * f0 + rs0; l1 = l1 * f1 + rs1;
        #pragma unroll
        for (int nf = 0; nf < 8; ++nf) {
            oacc[nf][0] *= f0; oacc[nf][1] *= f0;
            oacc[nf][2] *= f1; oacc[nf][3] *= f1;
        }
        const uint32_t vs_u = base_u + (uint32_t)(64 * FH) * 2;
        #pragma unroll
        for (int ks = 0; ks < 4; ++ks) {
            uint32_t af[4] = {
                pack_half(sacc[2 * ks][0],     sacc[2 * ks][1]),
                pack_half(sacc[2 * ks][2],     sacc[2 * ks][3]),
                pack_half(sacc[2 * ks + 1][0], sacc[2 * ks + 1][1]),
                pack_half(sacc[2 * ks + 1][2], sacc[2 * ks + 1][3])};
            #pragma unroll
            for (int p = 0; p < 4; ++p) {
                uint32_t r0v, r1v, r2v, r3v;
                uint32_t addr = vs_u +
                    ((uint32_t)((16 * ks + (lane & 7) + ((lane & 8) ? 8 : 0)) * FH
                                + p * 16 + ((lane & 16) ? 8 : 0)) << 1);
                LDSM_X4_T(r0v, r1v, r2v, r3v, addr);
                uint32_t b0[2] = {r0v, r1v}, b1[2] = {r2v, r3v};
                mma_fp16(oacc[2 * p],     af, b0);
                mma_fp16(oacc[2 * p + 1], af, b1);
            }
        }
    }

    float i0 = 1.0f / l0, i1 = 1.0f / l1;
    size_t orow = (size_t)(b * NN + qt * 128 + r0);
    uint32_t* O2 = reinterpret_cast<uint32_t*>(O);
    #pragma unroll
    for (int nf = 0; nf < 8; ++nf) {
        int col = h * 64 + nf * 8 + 2 * t;
        O2[(orow * CC + col) >> 1]       = pack_half(oacc[nf][0] * i0, oacc[nf][1] * i0);
        O2[((orow + 8) * CC + col) >> 1] = pack_half(oacc[nf][2] * i1, oacc[nf][3] * i1);
    }
}

// ---------------- 3D conv, z-slice blocks with SMEM halo ----------------
__global__ __launch_bounds__(256) void conv3d_z(const float* __restrict__ din,
                                                const float* __restrict__ cw,
                                                const float* __restrict__ cb,
                                                float* __restrict__ out) {
    __shared__ float ds[3][64][8];
    __shared__ float w[1728];
    __shared__ float bsh[8];
    const int zz = blockIdx.x;
    const int b = blockIdx.y;
    const int tid = threadIdx.x;

    for (int i = tid; i < 1728; i += 256) w[i] = cw[i];
    if (tid < 8) bsh[tid] = cb[tid];
    #pragma unroll
    for (int i = 0; i < 6; ++i) {
        int idx = tid + 256 * i;
        int dz = idx >> 9;
        int sp = (idx >> 3) & 63;
        int ch = idx & 7;
        int z = zz + dz - 1;
        float v = 0.f;
        if ((unsigned)z <= 7u)
            v = din[((size_t)b * 512 + z * 64 + sp) * 8 + ch];
        ds[dz][sp][ch] = v;
    }
    __syncthreads();

    #pragma unroll
    for (int it = 0; it < 2; ++it) {
        int idx = tid + 256 * it;
        int o = idx & 7;
        int sp = idx >> 3;
        int xx = sp & 7, yy = sp >> 3;
        float acc = bsh[o];
        #pragma unroll
        for (int dz = 0; dz < 3; ++dz) {
            #pragma unroll
            for (int dy = -1; dy <= 1; ++dy) {
                int y = yy + dy; if ((unsigned)y > 7u) continue;
                #pragma unroll
                for (int dx = -1; dx <= 1; ++dx) {
                    int xc = xx + dx; if ((unsigned)xc > 7u) continue;
                    const float* ip = ds[dz][y * 8 + xc];
                    const float* wp = w + o * 216 + (dz * 3 + (dy + 1)) * 3 + (dx + 1);
                    #pragma unroll
                    for (int i = 0; i < 8; ++i) acc += ip[i] * wp[i * 27];
                }
            }
        }
        out[((size_t)b * 512 + zz * 64 + sp) * 8 + o] = acc;
    }
}

// ---------------- launcher ----------------
static float* symaddr(const void* sym) {
    void* p = nullptr;
    cudaGetSymbolAddress(&p, sym);
    return (float*)p;
}

extern "C" void kernel_launch(void* const* d_in, const int* in_sizes, int n_in,
                              void* d_out, int out_size) {
    (void)in_sizes; (void)n_in; (void)out_size;
    const float* x      = (const float*)d_in[0];
    const float* pos    = (const float*)d_in[1];
    const float* ln1_g  = (const float*)d_in[2];
    const float* ln1_b  = (const float*)d_in[3];
    const float* qkv_w  = (const float*)d_in[4];
    const float* proj_w = (const float*)d_in[5];
    const float* proj_b = (const float*)d_in[6];
    const float* cp1_dw = (const float*)d_in[7];
    const float* cp1_db = (const float*)d_in[8];
    const float* cp1_cw = (const float*)d_in[9];
    const float* cp1_cb = (const float*)d_in[10];
    const float* cp1_uw = (const float*)d_in[11];
    const float* cp1_ub = (const float*)d_in[12];
    const float* ln2_g  = (const float*)d_in[13];
    const float* ln2_b  = (const float*)d_in[14];
    const float* ff_w1  = (const float*)d_in[15];
    const float* ff_b1  = (const float*)d_in[16];
    const float* ff_w2  = (const float*)d_in[17];
    const float* ff_b2  = (const float*)d_in[18];
    const float* cp2_dw = (const float*)d_in[19];
    const float* cp2_db = (const float*)d_in[20];
    const float* cp2_cw = (const float*)d_in[21];
    const float* cp2_cb = (const float*)d_in[22];
    const float* cp2_uw = (const float*)d_in[23];
    const float* cp2_ub = (const float*)d_in[24];
    float* out = (float*)d_out;

    float*  bx    = symaddr(g_x);
    __half* bh    = (__half*)symaddr(g_h);
    __half* bhb   = (__half*)symaddr(g_hb);
    __half* bqkv  = (__half*)symaddr(g_qkv);
    __half* bao   = (__half*)symaddr(g_ao);
    __half* bmlp  = (__half*)symaddr(g_mlp);
    float*  bd    = symaddr(g_d);
    float*  bc    = symaddr(g_c);
    __half* wqkvT = (__half*)symaddr(g_wqkvT);
    __half* wprojT= (__half*)symaddr(g_wprojT);
    __half* wff1T = (__half*)symaddr(g_wff1T);
    __half* wff2T = (__half*)symaddr(g_wff2T);

    cudaFuncSetAttribute(tc_gemm16<0,8>,  cudaFuncAttributeMaxDynamicSharedMemorySize, GEMM_SMEM);
    cudaFuncSetAttribute(tc_gemm16<1,8>,  cudaFuncAttributeMaxDynamicSharedMemorySize, GEMM_SMEM);
    cudaFuncSetAttribute(tc_gemm16<2,8>,  cudaFuncAttributeMaxDynamicSharedMemorySize, GEMM_SMEM);
    cudaFuncSetAttribute(tc_gemm16<2,64>, cudaFuncAttributeMaxDynamicSharedMemorySize, GEMM_SMEM);

    // all weight transposes in one launch
    transpose_all<<<5120, dim3(32, 8)>>>(qkv_w, wqkvT, proj_w, wprojT,
                                         ff_w1, wff1T, ff_w2, wff2T);

    // x = x + pos ; h = LN1(x) -> fp16 ; d1 = qgelu(h@dw1+db1)
    add_ln_down<<<MROWS, 256>>>(x, pos, ln1_g, ln1_b, cp1_dw, cp1_db, bx, bh, bd);
    conv3d_z<<<dim3(8, BB), 256>>>(bd, cp1_cw, cp1_cb, bc);

    // qkv = h @ qkv_w -> fp16   (K=512 -> NC=8)
    tc_gemm16<0,8><<<dim3(12, 128), 256, GEMM_SMEM>>>(bh, wqkvT, nullptr, bqkv,
                                                      MROWS, 3 * CC, CC,
                                                      nullptr, nullptr, nullptr, nullptr);
    // fused fp16 flash attention -> fp16
    flash_attn_h<<<dim3(4, BB * HH), 256>>>(bqkv, bao);

    // proj fused: x = x + (ao@projW + proj_b) + up1(qgelu(conv1)) + cp1_ub
    tc_gemm16<2,8><<<dim3(4, 128), 256, GEMM_SMEM>>>(bao, wprojT, proj_b, bx,
                                                     MROWS, CC, CC,
                                                     bx, bc, cp1_uw, cp1_ub);

    // h2 = LN2(x) -> fp16 ; d2 = qgelu(h2@dw2+db2)
    ln_h_down<<<MROWS, 256>>>(bx, ln2_g, ln2_b, cp2_dw, cp2_db, bhb, bd);
    conv3d_z<<<dim3(8, BB), 256>>>(bd, cp2_cw, cp2_cb, bc);

    // FFN fp16
    tc_gemm16<1,8><<<dim3(32, 128), 256, GEMM_SMEM>>>(bhb, wff1T, ff_b1, bmlp,
                                                      MROWS, MLPD, CC,
                                                      nullptr, nullptr, nullptr, nullptr);
    tc_gemm16<2,64><<<dim3(4, 128), 256, GEMM_SMEM>>>(bmlp, wff2T, ff_b2, out,
                                                      MROWS, CC, MLPD,
                                                      bx, bc, cp2_uw, cp2_ub);
}

// round 17
// speedup vs baseline: 1.0450x; 1.0223x over previous
#include <cuda_runtime.h>
#include <cuda_fp16.h>
#include <cstdint>

// ---------------- problem constants ----------------
#define BB    32
#define NN    512
#define CC    512
#define HH    8
#define DHD   64
#define ADIM  8
#define MLPD  4096
#define MROWS (BB*NN)          // 16384

// ---------------- static device scratch ----------------
__device__ __align__(16) float  g_x  [(size_t)MROWS*CC];
__device__ __align__(16) __half g_h  [(size_t)MROWS*CC];
__device__ __align__(16) __half g_hb [(size_t)MROWS*CC];
__device__ __align__(16) __half g_qkv[(size_t)MROWS*3*CC];
__device__ __align__(16) __half g_ao [(size_t)MROWS*CC];
__device__ __align__(16) __half g_mlp[(size_t)MROWS*MLPD];
__device__ __align__(16) float  g_d  [(size_t)MROWS*ADIM];
__device__ __align__(16) float  g_c  [(size_t)MROWS*ADIM];
__device__ __align__(16) __half g_wqkvT[(size_t)3*CC*CC];
__device__ __align__(16) __half g_wprojT[(size_t)CC*CC];
__device__ __align__(16) __half g_wff1T[(size_t)MLPD*CC];
__device__ __align__(16) __half g_wff2T[(size_t)CC*MLPD];

// ---------------- helpers ----------------
__device__ __forceinline__ float qgelu(float v) { return v / (1.0f + __expf(-1.702f * v)); }
__device__ __forceinline__ float gelu_exact(float v) { return 0.5f * v * (1.0f + erff(v * 0.70710678118654752f)); }
__device__ __forceinline__ float ex2(float x) {
    float r; asm("ex2.approx.f32 %0, %1;" : "=f"(r) : "f"(x)); return r;
}
__device__ __forceinline__ uint32_t smem_u32(const void* p) {
    uint32_t a;
    asm("{ .reg .u64 t; cvta.to.shared.u64 t, %1; cvt.u32.u64 %0, t; }" : "=r"(a) : "l"(p));
    return a;
}
__device__ __forceinline__ void cp16(uint32_t saddr, const void* g) {
    asm volatile("cp.async.cg.shared.global [%0], [%1], 16;" :: "r"(saddr), "l"(g));
}
__device__ __forceinline__ void mma_fp16(float d[4], const uint32_t a[4], const uint32_t b[2]) {
    asm volatile("mma.sync.aligned.m16n8k16.row.col.f32.f16.f16.f32 "
        "{%0,%1,%2,%3}, {%4,%5,%6,%7}, {%8,%9}, {%0,%1,%2,%3};"
        : "+f"(d[0]), "+f"(d[1]), "+f"(d[2]), "+f"(d[3])
        : "r"(a[0]), "r"(a[1]), "r"(a[2]), "r"(a[3]), "r"(b[0]), "r"(b[1]));
}
#define LDSM_X4(r0, r1, r2, r3, addr) \
    asm volatile("ldmatrix.sync.aligned.m8n8.x4.shared.b16 {%0,%1,%2,%3}, [%4];" \
        : "=r"(r0), "=r"(r1), "=r"(r2), "=r"(r3) : "r"(addr))
#define LDSM_X4_T(r0, r1, r2, r3, addr) \
    asm volatile("ldmatrix.sync.aligned.m8n8.x4.trans.shared.b16 {%0,%1,%2,%3}, [%4];" \
        : "=r"(r0), "=r"(r1), "=r"(r2), "=r"(r3) : "r"(addr))
__device__ __forceinline__ uint32_t pack_half(float a, float b) {
    __half2 v = __floats2half2_rn(a, b);
    return *reinterpret_cast<uint32_t*>(&v);
}

__device__ __forceinline__ float blockReduceSum256(float v) {
    __shared__ float sh[8];
    int lane = threadIdx.x & 31, w = threadIdx.x >> 5;
    #pragma unroll
    for (int o = 16; o > 0; o >>= 1) v += __shfl_down_sync(0xffffffffu, v, o);
    if (lane == 0) sh[w] = v;
    __syncthreads();
    if (threadIdx.x < 8) {
        float t = sh[threadIdx.x];
        t += __shfl_down_sync(0xffu, t, 4);
        t += __shfl_down_sync(0xffu, t, 2);
        t += __shfl_down_sync(0xffu, t, 1);
        if (threadIdx.x == 0) sh[0] = t;
    }
    __syncthreads();
    float r = sh[0];
    __syncthreads();
    return r;
}

__device__ __forceinline__ void downReduceStore(float p[8], const float* __restrict__ db,
                                                float* __restrict__ dout, size_t row) {
    __shared__ float sh8[8][8];
    int lane = threadIdx.x & 31, w = threadIdx.x >> 5;
    #pragma unroll
    for (int a = 0; a < 8; ++a) {
        #pragma unroll
        for (int o = 16; o > 0; o >>= 1)
            p[a] += __shfl_down_sync(0xffffffffu, p[a], o);
    }
    if (lane == 0) {
        #pragma unroll
        for (int a = 0; a < 8; ++a) sh8[w][a] = p[a];
    }
    __syncthreads();
    if (threadIdx.x < 8) {
        float s = 0.f;
        #pragma unroll
        for (int ww = 0; ww < 8; ++ww) s += sh8[ww][threadIdx.x];
        dout[row * 8 + threadIdx.x] = qgelu(s + db[threadIdx.x]);
    }
}

// ---------------- add+LN+down body (one row per block) ----------------
__device__ __forceinline__ void add_ln_down_body(size_t row,
                                                 const float* __restrict__ xin,
                                                 const float* __restrict__ pos,
                                                 const float* __restrict__ g,
                                                 const float* __restrict__ b,
                                                 const float* __restrict__ dw,
                                                 const float* __restrict__ db,
                                                 float* __restrict__ xout,
                                                 __half* __restrict__ hout,
                                                 float* __restrict__ dout) {
    int tid = threadIdx.x;
    float v0 = xin[row * CC + tid]       + pos[row * CC + tid];
    float v1 = xin[row * CC + tid + 256] + pos[row * CC + tid + 256];
    xout[row * CC + tid]       = v0;
    xout[row * CC + tid + 256] = v1;
    float mean = blockReduceSum256(v0 + v1) * (1.0f / 512.0f);
    float d0 = v0 - mean, d1 = v1 - mean;
    float var = blockReduceSum256(d0 * d0 + d1 * d1) * (1.0f / 512.0f);
    float inv = rsqrtf(var + 1e-5f);
    float h0 = d0 * inv * g[tid]       + b[tid];
    float h1 = d1 * inv * g[tid + 256] + b[tid + 256];
    hout[row * CC + tid]       = __float2half_rn(h0);
    hout[row * CC + tid + 256] = __float2half_rn(h1);
    float4 wA0 = *reinterpret_cast<const float4*>(dw + tid * 8);
    float4 wA1 = *reinterpret_cast<const float4*>(dw + tid * 8 + 4);
    float4 wB0 = *reinterpret_cast<const float4*>(dw + (tid + 256) * 8);
    float4 wB1 = *reinterpret_cast<const float4*>(dw + (tid + 256) * 8 + 4);
    float p[8];
    p[0] = h0 * wA0.x + h1 * wB0.x; p[1] = h0 * wA0.y + h1 * wB0.y;
    p[2] = h0 * wA0.z + h1 * wB0.z; p[3] = h0 * wA0.w + h1 * wB0.w;
    p[4] = h0 * wA1.x + h1 * wB1.x; p[5] = h0 * wA1.y + h1 * wB1.y;
    p[6] = h0 * wA1.z + h1 * wB1.z; p[7] = h0 * wA1.w + h1 * wB1.w;
    downReduceStore(p, db, dout, row);
}

// ---------------- transpose body (flat 256 threads) ----------------
__device__ __forceinline__ void transpose_body(int bid,
                                               const float* __restrict__ w0, __half* __restrict__ o0,
                                               const float* __restrict__ w1, __half* __restrict__ o1,
                                               const float* __restrict__ w2, __half* __restrict__ o2,
                                               const float* __restrict__ w3, __half* __restrict__ o3) {
    __shared__ float t[32][33];
    const float* in; __half* out; int R, Cc, tx, ty;
    if (bid < 768)        { in = w0; out = o0; R = 512;  Cc = 1536; int l = bid;        tx = l % 48;  ty = l / 48; }
    else if (bid < 1024)  { in = w1; out = o1; R = 512;  Cc = 512;  int l = bid - 768;  tx = l % 16;  ty = l / 16; }
    else if (bid < 3072)  { in = w2; out = o2; R = 512;  Cc = 4096; int l = bid - 1024; tx = l % 128; ty = l / 128; }
    else                  { in = w3; out = o3; R = 4096; Cc = 512;  int l = bid - 3072; tx = l % 16;  ty = l / 16; }
    int bx = tx * 32, by = ty * 32;
    int lx = threadIdx.x & 31, ly = threadIdx.x >> 5;   // 32 x 8
    #pragma unroll
    for (int i = 0; i < 32; i += 8)
        t[ly + i][lx] = in[(size_t)(by + ly + i) * Cc + bx + lx];
    __syncthreads();
    #pragma unroll
    for (int i = 0; i < 32; i += 8)
        out[(size_t)(bx + ly + i) * R + by + lx] = __float2half_rn(t[lx][ly + i]);
}

// ---------------- fused pre: add+LN1+down (16384 blocks) + transposes (5120) -------
__global__ __launch_bounds__(256) void fused_pre(const float* __restrict__ xin,
                                                 const float* __restrict__ pos,
                                                 const float* __restrict__ g,
                                                 const float* __restrict__ b,
                                                 const float* __restrict__ dw,
                                                 const float* __restrict__ db,
                                                 float* __restrict__ xout,
                                                 __half* __restrict__ hout,
                                                 float* __restrict__ dout,
                                                 const float* __restrict__ w0, __half* __restrict__ o0,
                                                 const float* __restrict__ w1, __half* __restrict__ o1,
                                                 const float* __restrict__ w2, __half* __restrict__ o2,
                                                 const float* __restrict__ w3, __half* __restrict__ o3) {
    if (blockIdx.x < MROWS) {
        add_ln_down_body(blockIdx.x, xin, pos, g, b, dw, db, xout, hout, dout);
    } else {
        transpose_body(blockIdx.x - MROWS, w0, o0, w1, o1, w2, o2, w3, o3);
    }
}

// ---------------- LN2 + adapter-down ----------------
__global__ __launch_bounds__(256) void ln_h_down(const float* __restrict__ in,
                                                 const float* __restrict__ g,
                                                 const float* __restrict__ b,
                                                 const float* __restrict__ dw,
                                                 const float* __restrict__ db,
                                                 __half* __restrict__ out,
                                                 float* __restrict__ dout) {
    size_t row = blockIdx.x;
    int tid = threadIdx.x;
    float v0 = in[row * CC + tid], v1 = in[row * CC + tid + 256];
    float mean = blockReduceSum256(v0 + v1) * (1.0f / 512.0f);
    float d0 = v0 - mean, d1 = v1 - mean;
    float var = blockReduceSum256(d0 * d0 + d1 * d1) * (1.0f / 512.0f);
    float inv = rsqrtf(var + 1e-5f);
    float h0 = d0 * inv * g[tid]       + b[tid];
    float h1 = d1 * inv * g[tid + 256] + b[tid + 256];
    out[row * CC + tid]       = __float2half_rn(h0);
    out[row * CC + tid + 256] = __float2half_rn(h1);
    float4 wA0 = *reinterpret_cast<const float4*>(dw + tid * 8);
    float4 wA1 = *reinterpret_cast<const float4*>(dw + tid * 8 + 4);
    float4 wB0 = *reinterpret_cast<const float4*>(dw + (tid + 256) * 8);
    float4 wB1 = *reinterpret_cast<const float4*>(dw + (tid + 256) * 8 + 4);
    float p[8];
    p[0] = h0 * wA0.x + h1 * wB0.x; p[1] = h0 * wA0.y + h1 * wB0.y;
    p[2] = h0 * wA0.z + h1 * wB0.z; p[3] = h0 * wA0.w + h1 * wB0.w;
    p[4] = h0 * wA1.x + h1 * wB1.x; p[5] = h0 * wA1.y + h1 * wB1.y;
    p[6] = h0 * wA1.z + h1 * wB1.z; p[7] = h0 * wA1.w + h1 * wB1.w;
    downReduceStore(p, db, dout, row);
}

// ---------------- 3D conv body (uses dynamic smem) ----------------
__device__ __forceinline__ void conv_body(char* smem, int cid,
                                          const float* __restrict__ din,
                                          const float* __restrict__ cw,
                                          const float* __restrict__ cb,
                                          float* __restrict__ out) {
    float (*ds)[64][8] = reinterpret_cast<float(*)[64][8]>(smem);           // 3*64*8
    float* w   = reinterpret_cast<float*>(smem + 3 * 64 * 8 * 4);           // 1728
    float* bsh = w + 1728;                                                  // 8
    const int zz = cid & 7;
    const int b  = cid >> 3;
    const int tid = threadIdx.x;

    for (int i = tid; i < 1728; i += 256) w[i] = cw[i];
    if (tid < 8) bsh[tid] = cb[tid];
    #pragma unroll
    for (int i = 0; i < 6; ++i) {
        int idx = tid + 256 * i;
        int dz = idx >> 9;
        int sp = (idx >> 3) & 63;
        int ch = idx & 7;
        int z = zz + dz - 1;
        float v = 0.f;
        if ((unsigned)z <= 7u)
            v = din[((size_t)b * 512 + z * 64 + sp) * 8 + ch];
        ds[dz][sp][ch] = v;
    }
    __syncthreads();

    #pragma unroll
    for (int it = 0; it < 2; ++it) {
        int idx = tid + 256 * it;
        int o = idx & 7;
        int sp = idx >> 3;
        int xx = sp & 7, yy = sp >> 3;
        float acc = bsh[o];
        #pragma unroll
        for (int dz = 0; dz < 3; ++dz) {
            #pragma unroll
            for (int dy = -1; dy <= 1; ++dy) {
                int y = yy + dy; if ((unsigned)y > 7u) continue;
                #pragma unroll
                for (int dx = -1; dx <= 1; ++dx) {
                    int xc = xx + dx; if ((unsigned)xc > 7u) continue;
                    const float* ip = ds[dz][y * 8 + xc];
                    const float* wp = w + o * 216 + (dz * 3 + (dy + 1)) * 3 + (dx + 1);
                    #pragma unroll
                    for (int i = 0; i < 8; ++i) acc += ip[i] * wp[i * 27];
                }
            }
        }
        out[((size_t)b * 512 + zz * 64 + sp) * 8 + o] = acc;
    }
}

// ---------------- fp16 mma GEMM (linear grid) + optional conv rider ---------------
// Full unroll for all NC. FC=1: blocks >= NB run 3D conv (256 extra blocks).
// EPI 0: plain -> fp16 (qkv). EPI 1: +bias +gelu -> fp16 (ff1).
// EPI 2: +(bias+ub) +res +adapter_up -> f32 (proj, ff2).
#define STG 32768
#define GEMM_SMEM (3*STG)      // 98304
template<int EPI, int NC, int FC>
__global__ __launch_bounds__(256, 2) void tc_gemm16(const __half* __restrict__ A,
                                                    const __half* __restrict__ BT,
                                                    const float* __restrict__ bias,
                                                    void* __restrict__ Cv,
                                                    int M, int N, int K,
                                                    const float* __restrict__ res,
                                                    const float* __restrict__ cpre,
                                                    const float* __restrict__ uw,
                                                    const float* __restrict__ ub,
                                                    const float* __restrict__ cvin,
                                                    const float* __restrict__ ccw,
                                                    const float* __restrict__ ccb,
                                                    float* __restrict__ cvout) {
    extern __shared__ char smem[];
    const int NBX = N >> 7;
    const int NB  = (M >> 7) * NBX;
    if (FC && (int)blockIdx.x >= NB) {
        conv_body(smem, (int)blockIdx.x - NB, cvin, ccw, ccb, cvout);
        return;
    }
    const uint32_t sb = smem_u32(smem);
    const int tid = threadIdx.x;
    const int lane = tid & 31;
    const int w = tid >> 5;
    const int wm = w & 1, wn = w >> 1;
    const int g = lane >> 2, t = lane & 3;
    const int cRow = ((int)blockIdx.x / NBX) * 128;
    const int cCol = ((int)blockIdx.x % NBX) * 128;

    const int r_st = tid >> 3;
    const int j_st = tid & 7;

    const int rb = lane & 7;
    const int a_row = wm * 64 + (lane & 15);
    const int a_j0  = lane >> 4;
    const int b_row = wn * 32 + (lane & 7) + ((lane & 16) ? 8 : 0);
    const int b_j0  = (lane >> 3) & 1;

    float acc[4][4][4] = {};

    auto stage = [&](int kt, uint32_t abase) {
        const int k0 = kt << 6;
        const uint32_t bbase = abase + 16384;
        #pragma unroll
        for (int i = 0; i < 4; ++i) {
            int r = r_st + i * 32;
            uint32_t phys = (uint32_t)r * 128 + ((uint32_t)(j_st ^ (r & 7)) << 4);
            cp16(abase + phys, A + (size_t)(cRow + r) * K + k0 + j_st * 8);
            cp16(bbase + phys, BT + (size_t)(cCol + r) * K + k0 + j_st * 8);
        }
        asm volatile("cp.async.commit_group;" ::: "memory");
    };

    stage(0, sb);
    stage(1, sb + STG);
    stage(2, sb + 2 * STG);
    asm volatile("cp.async.wait_group 2;" ::: "memory");
    __syncthreads();

    #pragma unroll
    for (int c = 0; c < NC; ++c) {
        const int s = c % 3;
        const uint32_t As_u = sb + s * STG;
        const uint32_t Bs_u = As_u + 16384;
        #pragma unroll
        for (int ks = 0; ks < 4; ++ks) {
            uint32_t af[4][4], bf[4][2];
            #pragma unroll
            for (int mf = 0; mf < 4; ++mf) {
                int row = a_row + mf * 16;
                uint32_t addr = As_u + (uint32_t)row * 128 +
                                ((uint32_t)((a_j0 + 2 * ks) ^ rb) << 4);
                LDSM_X4(af[mf][0], af[mf][1], af[mf][2], af[mf][3], addr);
            }
            #pragma unroll
            for (int p = 0; p < 2; ++p) {
                int row = b_row + p * 16;
                uint32_t addr = Bs_u + (uint32_t)row * 128 +
                                ((uint32_t)((b_j0 + 2 * ks) ^ rb) << 4);
                uint32_t r0, r1, r2, r3;
                LDSM_X4(r0, r1, r2, r3, addr);
                bf[2 * p][0] = r0; bf[2 * p][1] = r1;
                bf[2 * p + 1][0] = r2; bf[2 * p + 1][1] = r3;
            }
            #pragma unroll
            for (int mf = 0; mf < 4; ++mf)
                #pragma unroll
                for (int nf = 0; nf < 4; ++nf)
                    mma_fp16(acc[mf][nf], af[mf], bf[nf]);
        }
        if (c + 2 < NC)      { asm volatile("cp.async.wait_group 1;" ::: "memory"); }
        else if (c + 1 < NC) { asm volatile("cp.async.wait_group 0;" ::: "memory"); }
        __syncthreads();
        if (c + 3 < NC) stage(c + 3, As_u);
    }

    float* ush = (float*)smem;
    if (EPI == 2) {
        for (int i = tid; i < 4096; i += 256) ush[i] = uw[i];
        for (int i = tid; i < 512; i += 256) ush[4096 + i] = bias[i] + ub[i];
        __syncthreads();
    }

    #pragma unroll
    for (int mf = 0; mf < 4; ++mf) {
        size_t row0 = (size_t)(cRow + wm * 64 + mf * 16 + g);
        size_t row1 = row0 + 8;
        float p0[8], p1[8];
        if (EPI == 2) {
            float4 a0 = *reinterpret_cast<const float4*>(cpre + row0 * 8);
            float4 a1 = *reinterpret_cast<const float4*>(cpre + row0 * 8 + 4);
            float4 b0 = *reinterpret_cast<const float4*>(cpre + row1 * 8);
            float4 b1 = *reinterpret_cast<const float4*>(cpre + row1 * 8 + 4);
            p0[0]=qgelu(a0.x); p0[1]=qgelu(a0.y); p0[2]=qgelu(a0.z); p0[3]=qgelu(a0.w);
            p0[4]=qgelu(a1.x); p0[5]=qgelu(a1.y); p0[6]=qgelu(a1.z); p0[7]=qgelu(a1.w);
            p1[0]=qgelu(b0.x); p1[1]=qgelu(b0.y); p1[2]=qgelu(b0.z); p1[3]=qgelu(b0.w);
            p1[4]=qgelu(b1.x); p1[5]=qgelu(b1.y); p1[6]=qgelu(b1.z); p1[7]=qgelu(b1.w);
        }
        #pragma unroll
        for (int nf = 0; nf < 4; ++nf) {
            int col = cCol + wn * 32 + nf * 8 + 2 * t;
            if (EPI == 0) {
                uint32_t* C = (uint32_t*)Cv;
                C[(row0 * N + col) >> 1] = pack_half(acc[mf][nf][0], acc[mf][nf][1]);
                C[(row1 * N + col) >> 1] = pack_half(acc[mf][nf][2], acc[mf][nf][3]);
            } else if (EPI == 1) {
                float b0 = bias[col], b1 = bias[col + 1];
                uint32_t* C = (uint32_t*)Cv;
                C[(row0 * N + col) >> 1] =
                    pack_half(gelu_exact(acc[mf][nf][0] + b0), gelu_exact(acc[mf][nf][1] + b1));
                C[(row1 * N + col) >> 1] =
                    pack_half(gelu_exact(acc[mf][nf][2] + b0), gelu_exact(acc[mf][nf][3] + b1));
            } else {
                float u0 = ush[4096 + col], u1 = ush[4096 + col + 1];
                float u2 = u0, u3 = u1;
                #pragma unroll
                for (int a = 0; a < 8; ++a) {
                    float w0 = ush[a * 512 + col], w1 = ush[a * 512 + col + 1];
                    u0 += p0[a] * w0; u1 += p0[a] * w1;
                    u2 += p1[a] * w0; u3 += p1[a] * w1;
                }
                float2 r0 = *reinterpret_cast<const float2*>(&res[row0 * N + col]);
                float2 r1 = *reinterpret_cast<const float2*>(&res[row1 * N + col]);
                float* C = (float*)Cv;
                *reinterpret_cast<float2*>(&C[row0 * N + col]) =
                    make_float2(acc[mf][nf][0] + u0 + r0.x, acc[mf][nf][1] + u1 + r0.y);
                *reinterpret_cast<float2*>(&C[row1 * N + col]) =
                    make_float2(acc[mf][nf][2] + u2 + r1.x, acc[mf][nf][3] + u3 + r1.y);
            }
        }
    }
}

// ---------------- fused flash attention (fp16 mma, log2-domain softmax) ------------
#define FH 72
#define FA_C 0.180336880f      // 0.125 * log2(e)
__global__ __launch_bounds__(256) void flash_attn_h(const __half* __restrict__ qkv,
                                                    __half* __restrict__ O) {
    __shared__ __half fb[2 * 128 * FH];
    const int tid = threadIdx.x;
    const int lane = tid & 31;
    const int w = tid >> 5;
    const int g = lane >> 2, t = lane & 3;
    const int qt = blockIdx.x;
    const int bhid = blockIdx.y;
    const int b = bhid >> 3, h = bhid & 7;
    const int r0 = w * 16 + g;

    const uint32_t fb_u = smem_u32(fb);
    const __half* qptr = qkv + ((size_t)b * NN + qt * 128) * 1536 + h * 64;

    #pragma unroll
    for (int i = 0; i < 4; ++i) {
        int idx = tid + 256 * i;
        int r = idx >> 3, q = (idx & 7) * 8;
        *reinterpret_cast<uint4*>(fb + r * FH + q) =
            *reinterpret_cast<const uint4*>(qptr + (size_t)r * 1536 + q);
    }
    __syncthreads();
    uint32_t qf[4][4];
    {
        const uint32_t* Q2 = reinterpret_cast<const uint32_t*>(fb);
        #pragma unroll
        for (int ks = 0; ks < 4; ++ks) {
            int base = r0 * (FH / 2) + ks * 8 + t;
            qf[ks][0] = Q2[base];
            qf[ks][1] = Q2[base + 8 * (FH / 2)];
            qf[ks][2] = Q2[base + 4];
            qf[ks][3] = Q2[base + 8 * (FH / 2) + 4];
        }
    }
    __syncthreads();

    const __half* kptr = qkv + (size_t)b * NN * 1536 + 512 + h * 64;
    const __half* vptr = kptr + 512;
    const uint32_t kb_lane = ((uint32_t)((lane & 7) + ((lane & 16) ? 8 : 0)) * FH
                             + ((lane & 8) ? 8 : 0)) * 2;

    float oacc[8][4] = {};
    float m0 = -1e30f, m1 = -1e30f, l0 = 0.f, l1 = 0.f;

    for (int kt = 0; kt < 8; ++kt) {
        const uint32_t base_u = fb_u + (uint32_t)((kt & 1) * 128 * FH) * 2;
        __half* Kb = fb + (kt & 1) * 128 * FH;
        #pragma unroll
        for (int i = 0; i < 2; ++i) {
            int idx = tid + 256 * i;
            int r = idx >> 3, q = (idx & 7) * 8;
            size_t off = (size_t)(kt * 64 + r) * 1536 + q;
            *reinterpret_cast<uint4*>(Kb + r * FH + q) =
                *reinterpret_cast<const uint4*>(kptr + off);
            *reinterpret_cast<uint4*>(Kb + (64 + r) * FH + q) =
                *reinterpret_cast<const uint4*>(vptr + off);
        }
        __syncthreads();

        float sacc[8][4] = {};
        #pragma unroll
        for (int ks = 0; ks < 4; ++ks) {
            #pragma unroll
            for (int p = 0; p < 4; ++p) {
                uint32_t r0v, r1v, r2v, r3v;
                uint32_t addr = base_u + kb_lane +
                    ((uint32_t)(p * 16 * FH + ks * 16) << 1);
                LDSM_X4(r0v, r1v, r2v, r3v, addr);
                uint32_t b0[2] = {r0v, r1v}, b1[2] = {r2v, r3v};
                mma_fp16(sacc[2 * p],     qf[ks], b0);
                mma_fp16(sacc[2 * p + 1], qf[ks], b1);
            }
        }
        float mx0 = -1e30f, mx1 = -1e30f;
        #pragma unroll
        for (int nf = 0; nf < 8; ++nf) {
            mx0 = fmaxf(mx0, fmaxf(sacc[nf][0], sacc[nf][1]));
            mx1 = fmaxf(mx1, fmaxf(sacc[nf][2], sacc[nf][3]));
        }
        mx0 = fmaxf(mx0, __shfl_xor_sync(0xffffffffu, mx0, 1));
        mx0 = fmaxf(mx0, __shfl_xor_sync(0xffffffffu, mx0, 2));
        mx1 = fmaxf(mx1, __shfl_xor_sync(0xffffffffu, mx1, 1));
        mx1 = fmaxf(mx1, __shfl_xor_sync(0xffffffffu, mx1, 2));
        float mn0 = fmaxf(m0, mx0), mn1 = fmaxf(m1, mx1);
        float f0 = ex2((m0 - mn0) * FA_C), f1 = ex2((m1 - mn1) * FA_C);
        m0 = mn0; m1 = mn1;
        float nc0 = -mn0 * FA_C, nc1 = -mn1 * FA_C;
        float rs0 = 0.f, rs1 = 0.f;
        #pragma unroll
        for (int nf = 0; nf < 8; ++nf) {
            sacc[nf][0] = ex2(fmaf(sacc[nf][0], FA_C, nc0));
            sacc[nf][1] = ex2(fmaf(sacc[nf][1], FA_C, nc0));
            sacc[nf][2] = ex2(fmaf(sacc[nf][2], FA_C, nc1));
            sacc[nf][3] = ex2(fmaf(sacc[nf][3], FA_C, nc1));
            rs0 += sacc[nf][0] + sacc[nf][1];
            rs1 += sacc[nf][2] + sacc[nf][3];
        }
        rs0 += __shfl_xor_sync(0xffffffffu, rs0, 1);
        rs0 += __shfl_xor_sync(0xffffffffu, rs0, 2);
        rs1 += __shfl_xor_sync(0xffffffffu, rs1, 1);
        rs1 += __shfl_xor_sync(0xffffffffu, rs1, 2);
        l0 = l0 * f0 + rs0; l1 = l1 * f1 + rs1;
        #pragma unroll
        for (int nf = 0; nf < 8; ++nf) {
            oacc[nf][0] *= f0; oacc[nf][1] *= f0;
            oacc[nf][2] *= f1; oacc[nf][3] *= f1;
        }
        const uint32_t vs_u = base_u + (uint32_t)(64 * FH) * 2;
        #pragma unroll
        for (int ks = 0; ks < 4; ++ks) {
            uint32_t af[4] = {
                pack_half(sacc[2 * ks][0],     sacc[2 * ks][1]),
                pack_half(sacc[2 * ks][2],     sacc[2 * ks][3]),
                pack_half(sacc[2 * ks + 1][0], sacc[2 * ks + 1][1]),
                pack_half(sacc[2 * ks + 1][2], sacc[2 * ks + 1][3])};
            #pragma unroll
            for (int p = 0; p < 4; ++p) {
                uint32_t r0v, r1v, r2v, r3v;
                uint32_t addr = vs_u +
                    ((uint32_t)((16 * ks + (lane & 7) + ((lane & 8) ? 8 : 0)) * FH
                                + p * 16 + ((lane & 16) ? 8 : 0)) << 1);
                LDSM_X4_T(r0v, r1v, r2v, r3v, addr);
                uint32_t b0[2] = {r0v, r1v}, b1[2] = {r2v, r3v};
                mma_fp16(oacc[2 * p],     af, b0);
                mma_fp16(oacc[2 * p + 1], af, b1);
            }
        }
    }

    float i0 = 1.0f / l0, i1 = 1.0f / l1;
    size_t orow = (size_t)(b * NN + qt * 128 + r0);
    uint32_t* O2 = reinterpret_cast<uint32_t*>(O);
    #pragma unroll
    for (int nf = 0; nf < 8; ++nf) {
        int col = h * 64 + nf * 8 + 2 * t;
        O2[(orow * CC + col) >> 1]       = pack_half(oacc[nf][0] * i0, oacc[nf][1] * i0);
        O2[((orow + 8) * CC + col) >> 1] = pack_half(oacc[nf][2] * i1, oacc[nf][3] * i1);
    }
}

// ---------------- launcher ----------------
static float* symaddr(const void* sym) {
    void* p = nullptr;
    cudaGetSymbolAddress(&p, sym);
    return (float*)p;
}

extern "C" void kernel_launch(void* const* d_in, const int* in_sizes, int n_in,
                              void* d_out, int out_size) {
    (void)in_sizes; (void)n_in; (void)out_size;
    const float* x      = (const float*)d_in[0];
    const float* pos    = (const float*)d_in[1];
    const float* ln1_g  = (const float*)d_in[2];
    const float* ln1_b  = (const float*)d_in[3];
    const float* qkv_w  = (const float*)d_in[4];
    const float* proj_w = (const float*)d_in[5];
    const float* proj_b = (const float*)d_in[6];
    const float* cp1_dw = (const float*)d_in[7];
    const float* cp1_db = (const float*)d_in[8];
    const float* cp1_cw = (const float*)d_in[9];
    const float* cp1_cb = (const float*)d_in[10];
    const float* cp1_uw = (const float*)d_in[11];
    const float* cp1_ub = (const float*)d_in[12];
    const float* ln2_g  = (const float*)d_in[13];
    const float* ln2_b  = (const float*)d_in[14];
    const float* ff_w1  = (const float*)d_in[15];
    const float* ff_b1  = (const float*)d_in[16];
    const float* ff_w2  = (const float*)d_in[17];
    const float* ff_b2  = (const float*)d_in[18];
    const float* cp2_dw = (const float*)d_in[19];
    const float* cp2_db = (const float*)d_in[20];
    const float* cp2_cw = (const float*)d_in[21];
    const float* cp2_cb = (const float*)d_in[22];
    const float* cp2_uw = (const float*)d_in[23];
    const float* cp2_ub = (const float*)d_in[24];
    float* out = (float*)d_out;

    float*  bx    = symaddr(g_x);
    __half* bh    = (__half*)symaddr(g_h);
    __half* bhb   = (__half*)symaddr(g_hb);
    __half* bqkv  = (__half*)symaddr(g_qkv);
    __half* bao   = (__half*)symaddr(g_ao);
    __half* bmlp  = (__half*)symaddr(g_mlp);
    float*  bd    = symaddr(g_d);
    float*  bc    = symaddr(g_c);
    __half* wqkvT = (__half*)symaddr(g_wqkvT);
    __half* wprojT= (__half*)symaddr(g_wprojT);
    __half* wff1T = (__half*)symaddr(g_wff1T);
    __half* wff2T = (__half*)symaddr(g_wff2T);

    cudaFuncSetAttribute(tc_gemm16<0,8,1>,  cudaFuncAttributeMaxDynamicSharedMemorySize, GEMM_SMEM);
    cudaFuncSetAttribute(tc_gemm16<1,8,1>,  cudaFuncAttributeMaxDynamicSharedMemorySize, GEMM_SMEM);
    cudaFuncSetAttribute(tc_gemm16<2,8,0>,  cudaFuncAttributeMaxDynamicSharedMemorySize, GEMM_SMEM);
    cudaFuncSetAttribute(tc_gemm16<2,64,0>, cudaFuncAttributeMaxDynamicSharedMemorySize, GEMM_SMEM);

    // fused: x = x + pos ; h = LN1(x) ; d1 = qgelu(h@dw1+db1) ; all weight transposes
    fused_pre<<<MROWS + 5120, 256>>>(x, pos, ln1_g, ln1_b, cp1_dw, cp1_db,
                                     bx, bh, bd,
                                     qkv_w, wqkvT, proj_w, wprojT,
                                     ff_w1, wff1T, ff_w2, wff2T);

    // qkv = h @ qkv_w -> fp16  (+ conv1 rider blocks)
    tc_gemm16<0,8,1><<<1536 + 256, 256, GEMM_SMEM>>>(bh, wqkvT, nullptr, bqkv,
                                                     MROWS, 3 * CC, CC,
                                                     nullptr, nullptr, nullptr, nullptr,
                                                     bd, cp1_cw, cp1_cb, bc);
    // fused fp16 flash attention -> fp16
    flash_attn_h<<<dim3(4, BB * HH), 256>>>(bqkv, bao);

    // proj fused: x = x + (ao@projW + proj_b) + up1(qgelu(conv1)) + cp1_ub
    tc_gemm16<2,8,0><<<512, 256, GEMM_SMEM>>>(bao, wprojT, proj_b, bx,
                                              MROWS, CC, CC,
                                              bx, bc, cp1_uw, cp1_ub,
                                              nullptr, nullptr, nullptr, nullptr);

    // h2 = LN2(x) -> fp16 ; d2 = qgelu(h2@dw2+db2)
    ln_h_down<<<MROWS, 256>>>(bx, ln2_g, ln2_b, cp2_dw, cp2_db, bhb, bd);

    // ff1 (+ conv2 rider blocks)
    tc_gemm16<1,8,1><<<4096 + 256, 256, GEMM_SMEM>>>(bhb, wff1T, ff_b1, bmlp,
                                                     MROWS, MLPD, CC,
                                                     nullptr, nullptr, nullptr, nullptr,
                                                     bd, cp2_cw, cp2_cb, bc);
    // ff2 fused: out = x + (mlp@w2 + ff_b2) + up2(qgelu(conv2)) + cp2_ub
    tc_gemm16<2,64,0><<<512, 256, GEMM_SMEM>>>(bmlp, wff2T, ff_b2, out,
                                               MROWS, CC, MLPD,
                                               bx, bc, cp2_uw, cp2_ub,
                                               nullptr, nullptr, nullptr, nullptr);
}